// round 8
// baseline (speedup 1.0000x reference)
#include <cuda_runtime.h>
#include <cuda_bf16.h>
#include <math.h>
#include <stdint.h>

// Problem constants
#define B_  2
#define S_  2048
#define D_  1024
#define H_  16
#define DK_ 64

// GEMM tiling: 128x128 tile, 256 threads, 2-stage, 2 CTAs/SM
#define BM 128
#define BN 128
#define BK 32
#define KDIM 1024
#define CHUNKS 32
#define A_T 10240            // 128 x 40 x 2B
#define B_T 10240
#define BUF (2 * A_T + 2 * B_T)          // 40960
#define GEMM_SMEM (2 * BUF)              // 81920

// Attention smem: q-tile 128, 64-key tiles, 4 stages, 1 CTA/SM
#define SK 72
#define QT_B (128 * SK * 2)              // 18432
#define KT_B (64 * SK * 2)               // 9216
#define KVS_B (4 * KT_B)                 // 36864 per stage
#define QH_OFF 0
#define QL_OFF QT_B
#define KV_OFF(s, k) (2 * QT_B + (s) * KVS_B + (k) * KT_B)
#define MS_OFF (2 * QT_B + 4 * KVS_B)    // 184320
#define ATTN_SMEM (MS_OFF + 4 * 256)     // 185344

// Scratch (device globals)
__device__ __nv_bfloat16 g_qh[B_*S_*D_], g_ql[B_*S_*D_];
__device__ __nv_bfloat16 g_kh[B_*S_*D_], g_kl[B_*S_*D_];
__device__ __nv_bfloat16 g_vh[B_*S_*D_], g_vl[B_*S_*D_];
__device__ __nv_bfloat16 g_ch[B_*S_*D_], g_cl[B_*S_*D_];
__device__ __nv_bfloat16 g_aqh[B_*S_*D_], g_aql[B_*S_*D_];
__device__ __nv_bfloat16 g_akh[B_*S_*D_], g_akl[B_*S_*D_];
__device__ __nv_bfloat16 g_avh[B_*S_*D_], g_avl[B_*S_*D_];
__device__ __nv_bfloat16 g_wqh[D_*D_], g_wql[D_*D_];
__device__ __nv_bfloat16 g_wkh[D_*D_], g_wkl[D_*D_];
__device__ __nv_bfloat16 g_wvh[D_*D_], g_wvl[D_*D_];
__device__ __nv_bfloat16 g_woh[D_*D_], g_wol[D_*D_];

// ===========================================================================
// Helpers
// ===========================================================================
__device__ __forceinline__ uint32_t smem_u32(const void* p) {
    uint32_t a;
    asm("{ .reg .u64 t; cvta.to.shared.u64 t, %1; cvt.u32.u64 %0, t; }"
        : "=r"(a) : "l"(p));
    return a;
}
__device__ __forceinline__ void cp16(uint32_t dst, const void* src) {
    asm volatile("cp.async.cg.shared.global [%0], [%1], 16;" :: "r"(dst), "l"(src));
}
__device__ __forceinline__ void cp4(uint32_t dst, const void* src) {
    asm volatile("cp.async.ca.shared.global [%0], [%1], 4;" :: "r"(dst), "l"(src));
}
__device__ __forceinline__ void ldmx4(uint32_t& r0, uint32_t& r1,
                                      uint32_t& r2, uint32_t& r3, uint32_t addr) {
    asm volatile("ldmatrix.sync.aligned.m8n8.x4.shared.b16 {%0,%1,%2,%3}, [%4];"
                 : "=r"(r0), "=r"(r1), "=r"(r2), "=r"(r3) : "r"(addr));
}
__device__ __forceinline__ void ldmx4t(uint32_t& r0, uint32_t& r1,
                                       uint32_t& r2, uint32_t& r3, uint32_t addr) {
    asm volatile("ldmatrix.sync.aligned.m8n8.x4.trans.shared.b16 {%0,%1,%2,%3}, [%4];"
                 : "=r"(r0), "=r"(r1), "=r"(r2), "=r"(r3) : "r"(addr));
}
__device__ __forceinline__ void mma16816(float* c, const uint32_t* a,
                                         uint32_t b0, uint32_t b1) {
    asm volatile(
        "mma.sync.aligned.m16n8k16.row.col.f32.bf16.bf16.f32 "
        "{%0,%1,%2,%3}, {%4,%5,%6,%7}, {%8,%9}, {%0,%1,%2,%3};"
        : "+f"(c[0]), "+f"(c[1]), "+f"(c[2]), "+f"(c[3])
        : "r"(a[0]), "r"(a[1]), "r"(a[2]), "r"(a[3]), "r"(b0), "r"(b1));
}
__device__ __forceinline__ uint32_t pack2(unsigned short a, unsigned short b) {
    return (uint32_t)a | ((uint32_t)b << 16);
}
__device__ __forceinline__ uint32_t cvt2bf(float hi_elem, float lo_elem) {
    uint32_t r;
    asm("cvt.rn.bf16x2.f32 %0, %1, %2;" : "=r"(r) : "f"(hi_elem), "f"(lo_elem));
    return r;
}
__device__ __forceinline__ float bflo(uint32_t p) { return __uint_as_float(p << 16); }
__device__ __forceinline__ float bfhi(uint32_t p) { return __uint_as_float(p & 0xFFFF0000u); }
__device__ __forceinline__ float ex2f(float x) {
    float y; asm("ex2.approx.f32 %0, %1;" : "=f"(y) : "f"(x)); return y;
}

// ===========================================================================
// Split kernels (batched)
// ===========================================================================
__device__ __forceinline__ void split_one(const float* x, __nv_bfloat16* hi,
                                          __nv_bfloat16* lo, int i) {
    float4 v = ((const float4*)x)[i];
    float f[4] = {v.x, v.y, v.z, v.w};
    unsigned short h[4], l[4];
    #pragma unroll
    for (int j = 0; j < 4; j++) {
        __nv_bfloat16 bh = __float2bfloat16(f[j]);
        float r = f[j] - __bfloat162float(bh);
        h[j] = __bfloat16_as_ushort(bh);
        l[j] = __bfloat16_as_ushort(__float2bfloat16(r));
    }
    ((uint2*)hi)[i] = make_uint2(pack2(h[0], h[1]), pack2(h[2], h[3]));
    ((uint2*)lo)[i] = make_uint2(pack2(l[0], l[1]), pack2(l[2], l[3]));
}

__global__ __launch_bounds__(256) void split_acts(
    const float* __restrict__ q, const float* __restrict__ k, const float* __restrict__ v,
    __nv_bfloat16* qh, __nv_bfloat16* ql, __nv_bfloat16* kh, __nv_bfloat16* kl,
    __nv_bfloat16* vh, __nv_bfloat16* vl)
{
    int i = blockIdx.x * 256 + threadIdx.x;
    int z = blockIdx.y;
    const float* x = (z == 0) ? q : (z == 1) ? k : v;
    __nv_bfloat16* hi = (z == 0) ? qh : (z == 1) ? kh : vh;
    __nv_bfloat16* lo = (z == 0) ? ql : (z == 1) ? kl : vl;
    split_one(x, hi, lo, i);
}

__global__ __launch_bounds__(256) void split_weights(
    const float* __restrict__ w0, const float* __restrict__ w1,
    const float* __restrict__ w2, const float* __restrict__ w3,
    __nv_bfloat16* h0, __nv_bfloat16* l0, __nv_bfloat16* h1, __nv_bfloat16* l1,
    __nv_bfloat16* h2, __nv_bfloat16* l2, __nv_bfloat16* h3, __nv_bfloat16* l3)
{
    int i = blockIdx.x * 256 + threadIdx.x;
    int z = blockIdx.y;
    const float* x = (z == 0) ? w0 : (z == 1) ? w1 : (z == 2) ? w2 : w3;
    __nv_bfloat16* hi = (z == 0) ? h0 : (z == 1) ? h1 : (z == 2) ? h2 : h3;
    __nv_bfloat16* lo = (z == 0) ? l0 : (z == 1) ? l1 : (z == 2) ? l2 : l3;
    split_one(x, hi, lo, i);
}

// ===========================================================================
// GEMM (NT + bias): 128x128 tile, 256 threads, 2-stage, 2 CTAs/SM, z-batched.
// ===========================================================================
template<bool SPLIT>
__global__ __launch_bounds__(256, 2) void gemm3(
    const __nv_bfloat16* __restrict__ a0h, const __nv_bfloat16* __restrict__ a0l,
    const __nv_bfloat16* __restrict__ w0h, const __nv_bfloat16* __restrict__ w0l,
    const float* __restrict__ bias0,
    const __nv_bfloat16* __restrict__ a1h, const __nv_bfloat16* __restrict__ a1l,
    const __nv_bfloat16* __restrict__ w1h, const __nv_bfloat16* __restrict__ w1l,
    const float* __restrict__ bias1,
    const __nv_bfloat16* __restrict__ a2h, const __nv_bfloat16* __restrict__ a2l,
    const __nv_bfloat16* __restrict__ w2h, const __nv_bfloat16* __restrict__ w2l,
    const float* __restrict__ bias2,
    float* __restrict__ Cf,
    __nv_bfloat16* __restrict__ C0h, __nv_bfloat16* __restrict__ C0l,
    __nv_bfloat16* __restrict__ C1h, __nv_bfloat16* __restrict__ C1l,
    __nv_bfloat16* __restrict__ C2h, __nv_bfloat16* __restrict__ C2l)
{
    extern __shared__ char dynsm[];
    const uint32_t smb = smem_u32(dynsm);
    const int tid = threadIdx.x;
    const int l = tid & 31;
    const int wid = tid >> 5;
    const int wm = (wid & 3) * 32;
    const int wn = (wid >> 2) * 64;
    const int bm = blockIdx.y * BM;
    const int bn = blockIdx.x * BN;
    const int z = blockIdx.z;

    const __nv_bfloat16* aH = (z == 0) ? a0h : (z == 1) ? a1h : a2h;
    const __nv_bfloat16* aL = (z == 0) ? a0l : (z == 1) ? a1l : a2l;
    const __nv_bfloat16* bH = (z == 0) ? w0h : (z == 1) ? w1h : w2h;
    const __nv_bfloat16* bL = (z == 0) ? w0l : (z == 1) ? w1l : w2l;
    const float* bias = (z == 0) ? bias0 : (z == 1) ? bias1 : bias2;
    __nv_bfloat16* Chi = (z == 0) ? C0h : (z == 1) ? C1h : C2h;
    __nv_bfloat16* Clo = (z == 0) ? C0l : (z == 1) ? C1l : C2l;

    float acc[2][8][4];
    #pragma unroll
    for (int mi = 0; mi < 2; mi++)
        #pragma unroll
        for (int nj = 0; nj < 8; nj++)
            #pragma unroll
            for (int q = 0; q < 4; q++) acc[mi][nj][q] = 0.0f;

    auto issue = [&](int c, int buf) {
        const int kk = c * BK;
        const uint32_t base = smb + buf * BUF;
        #pragma unroll
        for (int i = 0; i < 2; i++) {
            int idx = tid + i * 256;
            int row = idx >> 2, s4 = (idx & 3) * 8;
            uint32_t off = (uint32_t)(row * 40 + s4) * 2;
            cp16(base + off,                   aH + (size_t)(bm + row) * KDIM + kk + s4);
            cp16(base + A_T + off,             aL + (size_t)(bm + row) * KDIM + kk + s4);
            cp16(base + 2 * A_T + off,         bH + (size_t)(bn + row) * KDIM + kk + s4);
            cp16(base + 2 * A_T + B_T + off,   bL + (size_t)(bn + row) * KDIM + kk + s4);
        }
        asm volatile("cp.async.commit_group;" ::: "memory");
    };

    auto compute = [&](int buf) {
        const uint32_t aBh = smb + buf * BUF;
        const uint32_t aBl = aBh + A_T;
        const uint32_t bBh = aBh + 2 * A_T;
        const uint32_t bBl = bBh + B_T;
        const int bmat = l >> 3, br8 = l & 7;
        #pragma unroll
        for (int ks = 0; ks < 2; ks++) {
            uint32_t ah[2][4], al[2][4];
            #pragma unroll
            for (int mi = 0; mi < 2; mi++) {
                uint32_t aoff = (uint32_t)((wm + mi * 16 + (l & 15)) * 40
                                           + ks * 16 + (l >> 4) * 8) * 2;
                ldmx4(ah[mi][0], ah[mi][1], ah[mi][2], ah[mi][3], aBh + aoff);
                ldmx4(al[mi][0], al[mi][1], al[mi][2], al[mi][3], aBl + aoff);
            }
            #pragma unroll
            for (int p = 0; p < 4; p++) {
                uint32_t boff = (uint32_t)((wn + p * 16 + ((bmat >> 1) << 3) + br8) * 40
                                           + ks * 16 + ((bmat & 1) << 3)) * 2;
                uint32_t bh0, bh1, bh2, bh3, bl0, bl1, bl2, bl3;
                ldmx4(bh0, bh1, bh2, bh3, bBh + boff);
                ldmx4(bl0, bl1, bl2, bl3, bBl + boff);
                #pragma unroll
                for (int mi = 0; mi < 2; mi++) {
                    mma16816(acc[mi][2 * p],     ah[mi], bh0, bh1);
                    mma16816(acc[mi][2 * p + 1], ah[mi], bh2, bh3);
                    mma16816(acc[mi][2 * p],     ah[mi], bl0, bl1);
                    mma16816(acc[mi][2 * p + 1], ah[mi], bl2, bl3);
                    mma16816(acc[mi][2 * p],     al[mi], bh0, bh1);
                    mma16816(acc[mi][2 * p + 1], al[mi], bh2, bh3);
                }
            }
        }
    };

    issue(0, 0);
    for (int c = 0; c < CHUNKS; ++c) {
        if (c + 1 < CHUNKS) {
            issue(c + 1, (c + 1) & 1);
            asm volatile("cp.async.wait_group 1;" ::: "memory");
        } else {
            asm volatile("cp.async.wait_group 0;" ::: "memory");
        }
        __syncthreads();
        compute(c & 1);
        __syncthreads();
    }

    #pragma unroll
    for (int mi = 0; mi < 2; mi++) {
        int r0 = bm + wm + mi * 16 + (l >> 2);
        #pragma unroll
        for (int nj = 0; nj < 8; nj++) {
            int col = bn + wn + nj * 8 + (l & 3) * 2;
            float2 bv = *(const float2*)&bias[col];
            float v0 = acc[mi][nj][0] + bv.x;
            float v1 = acc[mi][nj][1] + bv.y;
            float v2 = acc[mi][nj][2] + bv.x;
            float v3 = acc[mi][nj][3] + bv.y;
            if (SPLIT) {
                uint32_t ph = cvt2bf(v1, v0);
                uint32_t pl = cvt2bf(v1 - bfhi(ph), v0 - bflo(ph));
                *(uint32_t*)&Chi[(size_t)r0 * D_ + col] = ph;
                *(uint32_t*)&Clo[(size_t)r0 * D_ + col] = pl;
                ph = cvt2bf(v3, v2);
                pl = cvt2bf(v3 - bfhi(ph), v2 - bflo(ph));
                *(uint32_t*)&Chi[(size_t)(r0 + 8) * D_ + col] = ph;
                *(uint32_t*)&Clo[(size_t)(r0 + 8) * D_ + col] = pl;
            } else {
                *(float2*)&Cf[(size_t)r0 * D_ + col] = make_float2(v0, v1);
                *(float2*)&Cf[(size_t)(r0 + 8) * D_ + col] = make_float2(v2, v3);
            }
        }
    }
}

// ===========================================================================
// Tensor-core flash attention, software-pipelined:
// QK(t+1) issues before softmax(t) so tensor pipe overlaps exp/pack work.
// 4 KV stages, 1 CTA/SM, one barrier per tile.
// ===========================================================================
__global__ __launch_bounds__(256, 1) void attn_mma(
    const __nv_bfloat16* __restrict__ qHi, const __nv_bfloat16* __restrict__ qLo,
    const __nv_bfloat16* __restrict__ kHi, const __nv_bfloat16* __restrict__ kLo,
    const __nv_bfloat16* __restrict__ vHi, const __nv_bfloat16* __restrict__ vLo,
    const int* __restrict__ mask,
    __nv_bfloat16* __restrict__ cHi, __nv_bfloat16* __restrict__ cLo)
{
    extern __shared__ char dynsm[];
    const uint32_t smb = smem_u32(dynsm);
    const int tid = threadIdx.x;
    const int w = tid >> 5, l = tid & 31;
    const int b = blockIdx.z, h = blockIdx.y;
    const int q0 = blockIdx.x * 128;
    const size_t bS = (size_t)b * S_;
    const int hd = h * DK_;
    const float SC2 = 0.18033688011112042f;   // 0.125 * log2(e)

    auto load_q = [&](const __nv_bfloat16* g, uint32_t off) {
        #pragma unroll
        for (int t = 0; t < 4; t++) {
            int idx = tid + t * 256;
            int row = idx >> 3, seg = (idx & 7) * 8;
            cp16(smb + off + (uint32_t)(row * SK + seg) * 2,
                 g + (bS + q0 + row) * D_ + hd + seg);
        }
    };
    auto load_kv_tile = [&](const __nv_bfloat16* g, uint32_t off, int tok0) {
        #pragma unroll
        for (int t = 0; t < 2; t++) {
            int idx = tid + t * 256;
            int row = idx >> 3, seg = (idx & 7) * 8;
            cp16(smb + off + (uint32_t)(row * SK + seg) * 2,
                 g + (bS + tok0 + row) * D_ + hd + seg);
        }
    };
    auto load_kv = [&](int kt, int stg) {
        int tok0 = kt * 64;
        load_kv_tile(kHi, KV_OFF(stg, 0), tok0);
        load_kv_tile(kLo, KV_OFF(stg, 1), tok0);
        load_kv_tile(vHi, KV_OFF(stg, 2), tok0);
        load_kv_tile(vLo, KV_OFF(stg, 3), tok0);
        if (tid < 64) cp4(smb + MS_OFF + (uint32_t)(stg * 64 + tid) * 4,
                          mask + b * S_ + tok0 + tid);
    };

    float Oacc[8][4];
    #pragma unroll
    for (int nf = 0; nf < 8; nf++)
        #pragma unroll
        for (int q = 0; q < 4; q++) Oacc[nf][q] = 0.0f;
    float mrun0 = -1e30f, mrun1 = -1e30f, lrun0 = 0.0f, lrun1 = 0.0f;

    const uint32_t a_off = (uint32_t)((w * 16 + (l & 15)) * SK + ((l >> 4) << 3)) * 2;
    const int bmat = l >> 3, br8 = l & 7;

    // QK into given sacc for tile (stage = tile & 3)
    auto qk = [&](float (&sacc)[8][4], int tile) {
        const int stg = tile & 3;
        const uint32_t KhB = smb + KV_OFF(stg, 0), KlB = smb + KV_OFF(stg, 1);
        #pragma unroll
        for (int f = 0; f < 8; f++)
            #pragma unroll
            for (int q = 0; q < 4; q++) sacc[f][q] = 0.0f;
        #pragma unroll
        for (int kc = 0; kc < 4; kc++) {
            uint32_t aH[4], aL[4];
            ldmx4(aH[0], aH[1], aH[2], aH[3], smb + QH_OFF + a_off + kc * 32);
            ldmx4(aL[0], aL[1], aL[2], aL[3], smb + QL_OFF + a_off + kc * 32);
            #pragma unroll
            for (int np = 0; np < 4; np++) {
                uint32_t badr = (uint32_t)((np * 16 + ((bmat >> 1) << 3) + br8) * SK
                                           + kc * 16 + ((bmat & 1) << 3)) * 2;
                uint32_t bh0, bh1, bh2, bh3, bl0, bl1, bl2, bl3;
                ldmx4(bh0, bh1, bh2, bh3, KhB + badr);
                ldmx4(bl0, bl1, bl2, bl3, KlB + badr);
                mma16816(sacc[2 * np],     aH, bh0, bh1);
                mma16816(sacc[2 * np + 1], aH, bh2, bh3);
                mma16816(sacc[2 * np],     aH, bl0, bl1);
                mma16816(sacc[2 * np + 1], aH, bl2, bl3);
                mma16816(sacc[2 * np],     aL, bh0, bh1);
                mma16816(sacc[2 * np + 1], aL, bh2, bh3);
            }
        }
    };

    // softmax + PV for tile (consumes sacc)
    auto smpv = [&](float (&sacc)[8][4], int tile) {
        const int stg = tile & 3;
        const uint32_t VhB = smb + KV_OFF(stg, 2), VlB = smb + KV_OFF(stg, 3);
        const int* ms = (const int*)(dynsm + MS_OFF + stg * 256);

        float mx0 = -1e30f, mx1 = -1e30f;
        #pragma unroll
        for (int f = 0; f < 8; f++) {
            int c0 = f * 8 + (l & 3) * 2;
            int mk0 = ms[c0], mk1 = ms[c0 + 1];
            float t0 = mk0 ? sacc[f][0] * SC2 : -1e30f;
            float t1 = mk1 ? sacc[f][1] * SC2 : -1e30f;
            float t2 = mk0 ? sacc[f][2] * SC2 : -1e30f;
            float t3 = mk1 ? sacc[f][3] * SC2 : -1e30f;
            sacc[f][0] = t0; sacc[f][1] = t1; sacc[f][2] = t2; sacc[f][3] = t3;
            mx0 = fmaxf(mx0, fmaxf(t0, t1));
            mx1 = fmaxf(mx1, fmaxf(t2, t3));
        }
        mx0 = fmaxf(mx0, __shfl_xor_sync(0xffffffffu, mx0, 1));
        mx0 = fmaxf(mx0, __shfl_xor_sync(0xffffffffu, mx0, 2));
        mx1 = fmaxf(mx1, __shfl_xor_sync(0xffffffffu, mx1, 1));
        mx1 = fmaxf(mx1, __shfl_xor_sync(0xffffffffu, mx1, 2));
        float mn0 = fmaxf(mrun0, mx0), mn1 = fmaxf(mrun1, mx1);
        float cor0 = ex2f(mrun0 - mn0), cor1 = ex2f(mrun1 - mn1);
        mrun0 = mn0; mrun1 = mn1;
        float sum0 = 0.0f, sum1 = 0.0f;
        #pragma unroll
        for (int f = 0; f < 8; f++) {
            float p0 = ex2f(sacc[f][0] - mn0);
            float p1 = ex2f(sacc[f][1] - mn0);
            float p2 = ex2f(sacc[f][2] - mn1);
            float p3 = ex2f(sacc[f][3] - mn1);
            sacc[f][0] = p0; sacc[f][1] = p1; sacc[f][2] = p2; sacc[f][3] = p3;
            sum0 += p0 + p1; sum1 += p2 + p3;
        }
        sum0 += __shfl_xor_sync(0xffffffffu, sum0, 1);
        sum0 += __shfl_xor_sync(0xffffffffu, sum0, 2);
        sum1 += __shfl_xor_sync(0xffffffffu, sum1, 1);
        sum1 += __shfl_xor_sync(0xffffffffu, sum1, 2);
        lrun0 = lrun0 * cor0 + sum0;
        lrun1 = lrun1 * cor1 + sum1;
        #pragma unroll
        for (int nf = 0; nf < 8; nf++) {
            Oacc[nf][0] *= cor0; Oacc[nf][1] *= cor0;
            Oacc[nf][2] *= cor1; Oacc[nf][3] *= cor1;
        }

        #pragma unroll
        for (int kc2 = 0; kc2 < 4; kc2++) {
            const float* f0 = sacc[2 * kc2];
            const float* f1 = sacc[2 * kc2 + 1];
            uint32_t aH2[4], aL2[4];
            aH2[0] = cvt2bf(f0[1], f0[0]);
            aH2[1] = cvt2bf(f0[3], f0[2]);
            aH2[2] = cvt2bf(f1[1], f1[0]);
            aH2[3] = cvt2bf(f1[3], f1[2]);
            aL2[0] = cvt2bf(f0[1] - bfhi(aH2[0]), f0[0] - bflo(aH2[0]));
            aL2[1] = cvt2bf(f0[3] - bfhi(aH2[1]), f0[2] - bflo(aH2[1]));
            aL2[2] = cvt2bf(f1[1] - bfhi(aH2[2]), f1[0] - bflo(aH2[2]));
            aL2[3] = cvt2bf(f1[3] - bfhi(aH2[3]), f1[2] - bflo(aH2[3]));
            #pragma unroll
            for (int nf = 0; nf < 4; nf++) {
                uint32_t vadr = (uint32_t)((kc2 * 16 + (l & 15)) * SK
                                           + nf * 16 + ((l >> 4) << 3)) * 2;
                uint32_t vh0, vh1, vh2, vh3, vl0, vl1, vl2, vl3;
                ldmx4t(vh0, vh1, vh2, vh3, VhB + vadr);
                ldmx4t(vl0, vl1, vl2, vl3, VlB + vadr);
                mma16816(Oacc[2 * nf],     aH2, vh0, vh1);
                mma16816(Oacc[2 * nf + 1], aH2, vh2, vh3);
                mma16816(Oacc[2 * nf],     aH2, vl0, vl1);
                mma16816(Oacc[2 * nf + 1], aH2, vl2, vl3);
                mma16816(Oacc[2 * nf],     aL2, vh0, vh1);
                mma16816(Oacc[2 * nf + 1], aL2, vh2, vh3);
            }
        }
    };

    // Prologue: Q + tiles 0..2 into stages 0..2
    load_q(qHi, QH_OFF);
    load_q(qLo, QL_OFF);
    load_kv(0, 0);
    asm volatile("cp.async.commit_group;" ::: "memory");   // C0: Q + tile0
    load_kv(1, 1);
    asm volatile("cp.async.commit_group;" ::: "memory");   // C1
    load_kv(2, 2);
    asm volatile("cp.async.commit_group;" ::: "memory");   // C2
    asm volatile("cp.async.wait_group 2;" ::: "memory");   // C0 done
    __syncthreads();

    float sA[8][4], sB[8][4];
    qk(sA, 0);

    // One step: wait tile t+1; barrier; prefetch t+3; QK(t+1)->nxt; softmax+PV(t)
    auto step = [&](float (&cur)[8][4], float (&nxt)[8][4], int t) {
        asm volatile("cp.async.wait_group 1;" ::: "memory");   // tile t+1 arrived (this thread)
        __syncthreads();                                       // all threads arrived + stage (t+3)&3 free
        if (t + 3 < 32) load_kv(t + 3, (t + 3) & 3);
        asm volatile("cp.async.commit_group;" ::: "memory");
        if (t + 1 < 32) qk(nxt, t + 1);
        smpv(cur, t);
    };

    for (int t = 0; t < 32; t += 2) {
        step(sA, sB, t);
        step(sB, sA, t + 1);
    }

    // Epilogue
    const float inv0 = 1.0f / lrun0;
    const float inv1 = 1.0f / lrun1;
    const int r0 = q0 + w * 16 + (l >> 2);
    #pragma unroll
    for (int nf = 0; nf < 8; nf++) {
        int col = hd + nf * 8 + (l & 3) * 2;
        float v0 = Oacc[nf][0] * inv0, v1 = Oacc[nf][1] * inv0;
        uint32_t ph = cvt2bf(v1, v0);
        uint32_t pl = cvt2bf(v1 - bfhi(ph), v0 - bflo(ph));
        *(uint32_t*)&cHi[(bS + r0) * D_ + col] = ph;
        *(uint32_t*)&cLo[(bS + r0) * D_ + col] = pl;
        float v2 = Oacc[nf][2] * inv1, v3 = Oacc[nf][3] * inv1;
        ph = cvt2bf(v3, v2);
        pl = cvt2bf(v3 - bfhi(ph), v2 - bflo(ph));
        *(uint32_t*)&cHi[(bS + r0 + 8) * D_ + col] = ph;
        *(uint32_t*)&cLo[(bS + r0 + 8) * D_ + col] = pl;
    }
}

// ---------------------------------------------------------------------------
extern "C" void kernel_launch(void* const* d_in, const int* in_sizes, int n_in,
                              void* d_out, int out_size)
{
    (void)in_sizes; (void)n_in; (void)out_size;
    const float* query = (const float*)d_in[0];
    const float* key   = (const float*)d_in[1];
    const float* value = (const float*)d_in[2];
    const int*   mask  = (const int*)d_in[3];
    const float* Wq = (const float*)d_in[4];
    const float* bq = (const float*)d_in[5];
    const float* Wk = (const float*)d_in[6];
    const float* bk = (const float*)d_in[7];
    const float* Wv = (const float*)d_in[8];
    const float* bv = (const float*)d_in[9];
    const float* Wo = (const float*)d_in[10];
    const float* bo = (const float*)d_in[11];
    float* out = (float*)d_out;

    __nv_bfloat16 *qh, *ql, *kh, *kl, *vh, *vl, *ch, *cl;
    __nv_bfloat16 *aqh, *aql, *akh, *akl, *avh, *avl;
    __nv_bfloat16 *wqh, *wql, *wkh, *wkl, *wvh, *wvl, *woh, *wol;
    cudaGetSymbolAddress((void**)&qh, g_qh);   cudaGetSymbolAddress((void**)&ql, g_ql);
    cudaGetSymbolAddress((void**)&kh, g_kh);   cudaGetSymbolAddress((void**)&kl, g_kl);
    cudaGetSymbolAddress((void**)&vh, g_vh);   cudaGetSymbolAddress((void**)&vl, g_vl);
    cudaGetSymbolAddress((void**)&ch, g_ch);   cudaGetSymbolAddress((void**)&cl, g_cl);
    cudaGetSymbolAddress((void**)&aqh, g_aqh); cudaGetSymbolAddress((void**)&aql, g_aql);
    cudaGetSymbolAddress((void**)&akh, g_akh); cudaGetSymbolAddress((void**)&akl, g_akl);
    cudaGetSymbolAddress((void**)&avh, g_avh); cudaGetSymbolAddress((void**)&avl, g_avl);
    cudaGetSymbolAddress((void**)&wqh, g_wqh); cudaGetSymbolAddress((void**)&wql, g_wql);
    cudaGetSymbolAddress((void**)&wkh, g_wkh); cudaGetSymbolAddress((void**)&wkl, g_wkl);
    cudaGetSymbolAddress((void**)&wvh, g_wvh); cudaGetSymbolAddress((void**)&wvl, g_wvl);
    cudaGetSymbolAddress((void**)&woh, g_woh); cudaGetSymbolAddress((void**)&wol, g_wol);

    const int actN4 = B_ * S_ * D_ / 4;
    const int wN4   = D_ * D_ / 4;

    cudaFuncSetAttribute(gemm3<true>, cudaFuncAttributeMaxDynamicSharedMemorySize,
                         GEMM_SMEM);
    cudaFuncSetAttribute(gemm3<false>, cudaFuncAttributeMaxDynamicSharedMemorySize,
                         GEMM_SMEM);
    cudaFuncSetAttribute(attn_mma, cudaFuncAttributeMaxDynamicSharedMemorySize,
                         ATTN_SMEM);

    split_acts<<<dim3(actN4 / 256, 3), 256>>>(query, key, value,
                                              aqh, aql, akh, akl, avh, avl);
    split_weights<<<dim3(wN4 / 256, 4), 256>>>(Wq, Wk, Wv, Wo,
                                               wqh, wql, wkh, wkl,
                                               wvh, wvl, woh, wol);

    dim3 ggrid(D_ / BN, (B_ * S_) / BM, 3);
    gemm3<true><<<ggrid, 256, GEMM_SMEM>>>(
        aqh, aql, wqh, wql, bq,
        akh, akl, wkh, wkl, bk,
        avh, avl, wvh, wvl, bv,
        nullptr, qh, ql, kh, kl, vh, vl);

    dim3 agrid(S_ / 128, H_, B_);
    attn_mma<<<agrid, 256, ATTN_SMEM>>>(qh, ql, kh, kl, vh, vl, mask, ch, cl);

    dim3 ogrid(D_ / BN, (B_ * S_) / BM, 1);
    gemm3<false><<<ogrid, 256, GEMM_SMEM>>>(
        ch, cl, woh, wol, bo,
        ch, cl, woh, wol, bo,
        ch, cl, woh, wol, bo,
        out, nullptr, nullptr, nullptr, nullptr, nullptr, nullptr);
}

// round 9
// speedup vs baseline: 1.0355x; 1.0355x over previous
#include <cuda_runtime.h>
#include <cuda_bf16.h>
#include <math.h>
#include <stdint.h>

// Problem constants
#define B_  2
#define S_  2048
#define D_  1024
#define H_  16
#define DK_ 64

// GEMM tiling: 128x128 tile, 256 threads, 2-stage, 2 CTAs/SM
#define BM 128
#define BN 128
#define BK 32
#define KDIM 1024
#define CHUNKS 32
#define A_T 10240            // 128 x 40 x 2B
#define B_T 10240
#define BUF (2 * A_T + 2 * B_T)          // 40960
#define GEMM_SMEM (2 * BUF)              // 81920

// Attention smem layout (64-key tiles, 2 CTAs/SM)
#define SK 72
#define QT_B (128 * SK * 2)              // 18432
#define KT_B (64 * SK * 2)               // 9216
#define QH_OFF 0
#define QL_OFF QT_B
#define KV_OFF(buf, t) (2 * QT_B + (buf) * 4 * KT_B + (t) * KT_B)
#define MS_OFF (2 * QT_B + 8 * KT_B)     // 110592
#define FLAG_OFF (MS_OFF + 512)          // 111104
#define ATTN_SMEM (FLAG_OFF + 128)       // 111232

// Scratch (device globals)
__device__ __nv_bfloat16 g_qh[B_*S_*D_], g_ql[B_*S_*D_];
__device__ __nv_bfloat16 g_kh[B_*S_*D_], g_kl[B_*S_*D_];
__device__ __nv_bfloat16 g_vh[B_*S_*D_], g_vl[B_*S_*D_];
__device__ __nv_bfloat16 g_ch[B_*S_*D_], g_cl[B_*S_*D_];
__device__ __nv_bfloat16 g_aqh[B_*S_*D_], g_aql[B_*S_*D_];
__device__ __nv_bfloat16 g_akh[B_*S_*D_], g_akl[B_*S_*D_];
__device__ __nv_bfloat16 g_avh[B_*S_*D_], g_avl[B_*S_*D_];
__device__ __nv_bfloat16 g_wqh[D_*D_], g_wql[D_*D_];
__device__ __nv_bfloat16 g_wkh[D_*D_], g_wkl[D_*D_];
__device__ __nv_bfloat16 g_wvh[D_*D_], g_wvl[D_*D_];
__device__ __nv_bfloat16 g_woh[D_*D_], g_wol[D_*D_];

// ===========================================================================
// Helpers
// ===========================================================================
__device__ __forceinline__ uint32_t smem_u32(const void* p) {
    uint32_t a;
    asm("{ .reg .u64 t; cvta.to.shared.u64 t, %1; cvt.u32.u64 %0, t; }"
        : "=r"(a) : "l"(p));
    return a;
}
__device__ __forceinline__ void cp16(uint32_t dst, const void* src) {
    asm volatile("cp.async.cg.shared.global [%0], [%1], 16;" :: "r"(dst), "l"(src));
}
__device__ __forceinline__ void cp4(uint32_t dst, const void* src) {
    asm volatile("cp.async.ca.shared.global [%0], [%1], 4;" :: "r"(dst), "l"(src));
}
__device__ __forceinline__ void ldmx4(uint32_t& r0, uint32_t& r1,
                                      uint32_t& r2, uint32_t& r3, uint32_t addr) {
    asm volatile("ldmatrix.sync.aligned.m8n8.x4.shared.b16 {%0,%1,%2,%3}, [%4];"
                 : "=r"(r0), "=r"(r1), "=r"(r2), "=r"(r3) : "r"(addr));
}
__device__ __forceinline__ void ldmx4t(uint32_t& r0, uint32_t& r1,
                                       uint32_t& r2, uint32_t& r3, uint32_t addr) {
    asm volatile("ldmatrix.sync.aligned.m8n8.x4.trans.shared.b16 {%0,%1,%2,%3}, [%4];"
                 : "=r"(r0), "=r"(r1), "=r"(r2), "=r"(r3) : "r"(addr));
}
__device__ __forceinline__ void mma16816(float* c, const uint32_t* a,
                                         uint32_t b0, uint32_t b1) {
    asm volatile(
        "mma.sync.aligned.m16n8k16.row.col.f32.bf16.bf16.f32 "
        "{%0,%1,%2,%3}, {%4,%5,%6,%7}, {%8,%9}, {%0,%1,%2,%3};"
        : "+f"(c[0]), "+f"(c[1]), "+f"(c[2]), "+f"(c[3])
        : "r"(a[0]), "r"(a[1]), "r"(a[2]), "r"(a[3]), "r"(b0), "r"(b1));
}
__device__ __forceinline__ uint32_t pack2(unsigned short a, unsigned short b) {
    return (uint32_t)a | ((uint32_t)b << 16);
}
__device__ __forceinline__ uint32_t cvt2bf(float hi_elem, float lo_elem) {
    uint32_t r;
    asm("cvt.rn.bf16x2.f32 %0, %1, %2;" : "=r"(r) : "f"(hi_elem), "f"(lo_elem));
    return r;
}
__device__ __forceinline__ float bflo(uint32_t p) { return __uint_as_float(p << 16); }
__device__ __forceinline__ float bfhi(uint32_t p) { return __uint_as_float(p & 0xFFFF0000u); }
__device__ __forceinline__ float ex2f(float x) {
    float y; asm("ex2.approx.f32 %0, %1;" : "=f"(y) : "f"(x)); return y;
}

// ===========================================================================
// Split kernels (batched)
// ===========================================================================
__device__ __forceinline__ void split_one(const float* x, __nv_bfloat16* hi,
                                          __nv_bfloat16* lo, int i) {
    float4 v = ((const float4*)x)[i];
    float f[4] = {v.x, v.y, v.z, v.w};
    unsigned short h[4], l[4];
    #pragma unroll
    for (int j = 0; j < 4; j++) {
        __nv_bfloat16 bh = __float2bfloat16(f[j]);
        float r = f[j] - __bfloat162float(bh);
        h[j] = __bfloat16_as_ushort(bh);
        l[j] = __bfloat16_as_ushort(__float2bfloat16(r));
    }
    ((uint2*)hi)[i] = make_uint2(pack2(h[0], h[1]), pack2(h[2], h[3]));
    ((uint2*)lo)[i] = make_uint2(pack2(l[0], l[1]), pack2(l[2], l[3]));
}

__global__ __launch_bounds__(256) void split_acts(
    const float* __restrict__ q, const float* __restrict__ k, const float* __restrict__ v,
    __nv_bfloat16* qh, __nv_bfloat16* ql, __nv_bfloat16* kh, __nv_bfloat16* kl,
    __nv_bfloat16* vh, __nv_bfloat16* vl)
{
    int i = blockIdx.x * 256 + threadIdx.x;
    int z = blockIdx.y;
    const float* x = (z == 0) ? q : (z == 1) ? k : v;
    __nv_bfloat16* hi = (z == 0) ? qh : (z == 1) ? kh : vh;
    __nv_bfloat16* lo = (z == 0) ? ql : (z == 1) ? kl : vl;
    split_one(x, hi, lo, i);
}

__global__ __launch_bounds__(256) void split_weights(
    const float* __restrict__ w0, const float* __restrict__ w1,
    const float* __restrict__ w2, const float* __restrict__ w3,
    __nv_bfloat16* h0, __nv_bfloat16* l0, __nv_bfloat16* h1, __nv_bfloat16* l1,
    __nv_bfloat16* h2, __nv_bfloat16* l2, __nv_bfloat16* h3, __nv_bfloat16* l3)
{
    int i = blockIdx.x * 256 + threadIdx.x;
    int z = blockIdx.y;
    const float* x = (z == 0) ? w0 : (z == 1) ? w1 : (z == 2) ? w2 : w3;
    __nv_bfloat16* hi = (z == 0) ? h0 : (z == 1) ? h1 : (z == 2) ? h2 : h3;
    __nv_bfloat16* lo = (z == 0) ? l0 : (z == 1) ? l1 : (z == 2) ? l2 : l3;
    split_one(x, hi, lo, i);
}

// ===========================================================================
// GEMM (NT + bias, optional output scale): 128x128, 256 thr, 2 CTAs/SM.
// ===========================================================================
template<bool SPLIT>
__global__ __launch_bounds__(256, 2) void gemm3(
    const __nv_bfloat16* __restrict__ a0h, const __nv_bfloat16* __restrict__ a0l,
    const __nv_bfloat16* __restrict__ w0h, const __nv_bfloat16* __restrict__ w0l,
    const float* __restrict__ bias0,
    const __nv_bfloat16* __restrict__ a1h, const __nv_bfloat16* __restrict__ a1l,
    const __nv_bfloat16* __restrict__ w1h, const __nv_bfloat16* __restrict__ w1l,
    const float* __restrict__ bias1,
    const __nv_bfloat16* __restrict__ a2h, const __nv_bfloat16* __restrict__ a2l,
    const __nv_bfloat16* __restrict__ w2h, const __nv_bfloat16* __restrict__ w2l,
    const float* __restrict__ bias2,
    float s0, float s1, float s2,
    float* __restrict__ Cf,
    __nv_bfloat16* __restrict__ C0h, __nv_bfloat16* __restrict__ C0l,
    __nv_bfloat16* __restrict__ C1h, __nv_bfloat16* __restrict__ C1l,
    __nv_bfloat16* __restrict__ C2h, __nv_bfloat16* __restrict__ C2l)
{
    extern __shared__ char dynsm[];
    const uint32_t smb = smem_u32(dynsm);
    const int tid = threadIdx.x;
    const int l = tid & 31;
    const int wid = tid >> 5;
    const int wm = (wid & 3) * 32;
    const int wn = (wid >> 2) * 64;
    const int bm = blockIdx.y * BM;
    const int bn = blockIdx.x * BN;
    const int z = blockIdx.z;

    const __nv_bfloat16* aH = (z == 0) ? a0h : (z == 1) ? a1h : a2h;
    const __nv_bfloat16* aL = (z == 0) ? a0l : (z == 1) ? a1l : a2l;
    const __nv_bfloat16* bH = (z == 0) ? w0h : (z == 1) ? w1h : w2h;
    const __nv_bfloat16* bL = (z == 0) ? w0l : (z == 1) ? w1l : w2l;
    const float* bias = (z == 0) ? bias0 : (z == 1) ? bias1 : bias2;
    const float osc = (z == 0) ? s0 : (z == 1) ? s1 : s2;
    __nv_bfloat16* Chi = (z == 0) ? C0h : (z == 1) ? C1h : C2h;
    __nv_bfloat16* Clo = (z == 0) ? C0l : (z == 1) ? C1l : C2l;

    float acc[2][8][4];
    #pragma unroll
    for (int mi = 0; mi < 2; mi++)
        #pragma unroll
        for (int nj = 0; nj < 8; nj++)
            #pragma unroll
            for (int q = 0; q < 4; q++) acc[mi][nj][q] = 0.0f;

    auto issue = [&](int c, int buf) {
        const int kk = c * BK;
        const uint32_t base = smb + buf * BUF;
        #pragma unroll
        for (int i = 0; i < 2; i++) {
            int idx = tid + i * 256;
            int row = idx >> 2, s4 = (idx & 3) * 8;
            uint32_t off = (uint32_t)(row * 40 + s4) * 2;
            cp16(base + off,                   aH + (size_t)(bm + row) * KDIM + kk + s4);
            cp16(base + A_T + off,             aL + (size_t)(bm + row) * KDIM + kk + s4);
            cp16(base + 2 * A_T + off,         bH + (size_t)(bn + row) * KDIM + kk + s4);
            cp16(base + 2 * A_T + B_T + off,   bL + (size_t)(bn + row) * KDIM + kk + s4);
        }
        asm volatile("cp.async.commit_group;" ::: "memory");
    };

    auto compute = [&](int buf) {
        const uint32_t aBh = smb + buf * BUF;
        const uint32_t aBl = aBh + A_T;
        const uint32_t bBh = aBh + 2 * A_T;
        const uint32_t bBl = bBh + B_T;
        const int bmat = l >> 3, br8 = l & 7;
        #pragma unroll
        for (int ks = 0; ks < 2; ks++) {
            uint32_t ah[2][4], al[2][4];
            #pragma unroll
            for (int mi = 0; mi < 2; mi++) {
                uint32_t aoff = (uint32_t)((wm + mi * 16 + (l & 15)) * 40
                                           + ks * 16 + (l >> 4) * 8) * 2;
                ldmx4(ah[mi][0], ah[mi][1], ah[mi][2], ah[mi][3], aBh + aoff);
                ldmx4(al[mi][0], al[mi][1], al[mi][2], al[mi][3], aBl + aoff);
            }
            #pragma unroll
            for (int p = 0; p < 4; p++) {
                uint32_t boff = (uint32_t)((wn + p * 16 + ((bmat >> 1) << 3) + br8) * 40
                                           + ks * 16 + ((bmat & 1) << 3)) * 2;
                uint32_t bh0, bh1, bh2, bh3, bl0, bl1, bl2, bl3;
                ldmx4(bh0, bh1, bh2, bh3, bBh + boff);
                ldmx4(bl0, bl1, bl2, bl3, bBl + boff);
                #pragma unroll
                for (int mi = 0; mi < 2; mi++) {
                    mma16816(acc[mi][2 * p],     ah[mi], bh0, bh1);
                    mma16816(acc[mi][2 * p + 1], ah[mi], bh2, bh3);
                    mma16816(acc[mi][2 * p],     ah[mi], bl0, bl1);
                    mma16816(acc[mi][2 * p + 1], ah[mi], bl2, bl3);
                    mma16816(acc[mi][2 * p],     al[mi], bh0, bh1);
                    mma16816(acc[mi][2 * p + 1], al[mi], bh2, bh3);
                }
            }
        }
    };

    issue(0, 0);
    for (int c = 0; c < CHUNKS; ++c) {
        if (c + 1 < CHUNKS) {
            issue(c + 1, (c + 1) & 1);
            asm volatile("cp.async.wait_group 1;" ::: "memory");
        } else {
            asm volatile("cp.async.wait_group 0;" ::: "memory");
        }
        __syncthreads();
        compute(c & 1);
        __syncthreads();
    }

    #pragma unroll
    for (int mi = 0; mi < 2; mi++) {
        int r0 = bm + wm + mi * 16 + (l >> 2);
        #pragma unroll
        for (int nj = 0; nj < 8; nj++) {
            int col = bn + wn + nj * 8 + (l & 3) * 2;
            float2 bv = *(const float2*)&bias[col];
            float v0 = (acc[mi][nj][0] + bv.x) * osc;
            float v1 = (acc[mi][nj][1] + bv.y) * osc;
            float v2 = (acc[mi][nj][2] + bv.x) * osc;
            float v3 = (acc[mi][nj][3] + bv.y) * osc;
            if (SPLIT) {
                uint32_t ph = cvt2bf(v1, v0);
                uint32_t pl = cvt2bf(v1 - bfhi(ph), v0 - bflo(ph));
                *(uint32_t*)&Chi[(size_t)r0 * D_ + col] = ph;
                *(uint32_t*)&Clo[(size_t)r0 * D_ + col] = pl;
                ph = cvt2bf(v3, v2);
                pl = cvt2bf(v3 - bfhi(ph), v2 - bflo(ph));
                *(uint32_t*)&Chi[(size_t)(r0 + 8) * D_ + col] = ph;
                *(uint32_t*)&Clo[(size_t)(r0 + 8) * D_ + col] = pl;
            } else {
                *(float2*)&Cf[(size_t)r0 * D_ + col] = make_float2(v0, v1);
                *(float2*)&Cf[(size_t)(r0 + 8) * D_ + col] = make_float2(v2, v3);
            }
        }
    }
}

// ===========================================================================
// Tensor-core flash attention (bf16 hi/lo, exp2-domain softmax).
// 64-key tiles, 2 CTAs/SM. Q pre-scaled by 0.125*log2(e) at projection.
// Per-tile all-ones mask flags skip masking work on the fast path.
// ===========================================================================
__global__ __launch_bounds__(256, 2) void attn_mma(
    const __nv_bfloat16* __restrict__ qHi, const __nv_bfloat16* __restrict__ qLo,
    const __nv_bfloat16* __restrict__ kHi, const __nv_bfloat16* __restrict__ kLo,
    const __nv_bfloat16* __restrict__ vHi, const __nv_bfloat16* __restrict__ vLo,
    const int* __restrict__ mask,
    __nv_bfloat16* __restrict__ cHi, __nv_bfloat16* __restrict__ cLo)
{
    extern __shared__ char dynsm[];
    const uint32_t smb = smem_u32(dynsm);
    const int tid = threadIdx.x;
    const int w = tid >> 5, l = tid & 31;
    const int b = blockIdx.z, h = blockIdx.y;
    const int q0 = blockIdx.x * 128;
    const size_t bS = (size_t)b * S_;
    const int hd = h * DK_;

    // Per-tile all-ones flags (32 tiles, 64 mask ints each)
    {
        const int4* mp = (const int4*)(mask + b * S_);
        int4 a = mp[tid * 2];
        int4 c = mp[tid * 2 + 1];
        int allm = a.x & a.y & a.z & a.w & c.x & c.y & c.z & c.w;
        allm &= __shfl_xor_sync(0xffffffffu, allm, 1);
        allm &= __shfl_xor_sync(0xffffffffu, allm, 2);
        allm &= __shfl_xor_sync(0xffffffffu, allm, 4);
        if ((tid & 7) == 0)
            ((int*)(dynsm + FLAG_OFF))[tid >> 3] = allm;
    }

    auto load_q = [&](const __nv_bfloat16* g, uint32_t off) {
        #pragma unroll
        for (int t = 0; t < 4; t++) {
            int idx = tid + t * 256;
            int row = idx >> 3, seg = (idx & 7) * 8;
            cp16(smb + off + (uint32_t)(row * SK + seg) * 2,
                 g + (bS + q0 + row) * D_ + hd + seg);
        }
    };
    auto load_kv_tile = [&](const __nv_bfloat16* g, uint32_t off, int tok0) {
        #pragma unroll
        for (int t = 0; t < 2; t++) {
            int idx = tid + t * 256;
            int row = idx >> 3, seg = (idx & 7) * 8;
            cp16(smb + off + (uint32_t)(row * SK + seg) * 2,
                 g + (bS + tok0 + row) * D_ + hd + seg);
        }
    };
    auto load_kv = [&](int kt, int buf) {
        int tok0 = kt * 64;
        load_kv_tile(kHi, KV_OFF(buf, 0), tok0);
        load_kv_tile(kLo, KV_OFF(buf, 1), tok0);
        load_kv_tile(vHi, KV_OFF(buf, 2), tok0);
        load_kv_tile(vLo, KV_OFF(buf, 3), tok0);
        if (tid < 64) cp4(smb + MS_OFF + (uint32_t)(buf * 64 + tid) * 4,
                          mask + b * S_ + tok0 + tid);
    };

    load_q(qHi, QH_OFF);
    load_q(qLo, QL_OFF);
    load_kv(0, 0);
    asm volatile("cp.async.commit_group;" ::: "memory");

    float Oacc[8][4];
    #pragma unroll
    for (int nf = 0; nf < 8; nf++)
        #pragma unroll
        for (int q = 0; q < 4; q++) Oacc[nf][q] = 0.0f;
    float mrun0 = -1e30f, mrun1 = -1e30f, lrun0 = 0.0f, lrun1 = 0.0f;

    const uint32_t a_off = (uint32_t)((w * 16 + (l & 15)) * SK + ((l >> 4) << 3)) * 2;
    const int bmat = l >> 3, br8 = l & 7;

    for (int kt = 0; kt < 32; kt++) {
        const int buf = kt & 1;
        if (kt < 31) {
            load_kv(kt + 1, buf ^ 1);
            asm volatile("cp.async.commit_group;" ::: "memory");
            asm volatile("cp.async.wait_group 1;" ::: "memory");
        } else {
            asm volatile("cp.async.wait_group 0;" ::: "memory");
        }
        __syncthreads();

        const uint32_t KhB = smb + KV_OFF(buf, 0), KlB = smb + KV_OFF(buf, 1);
        const uint32_t VhB = smb + KV_OFF(buf, 2), VlB = smb + KV_OFF(buf, 3);

        float sacc[8][4];
        #pragma unroll
        for (int f = 0; f < 8; f++)
            #pragma unroll
            for (int q = 0; q < 4; q++) sacc[f][q] = 0.0f;

        // ---- S = Q K^T (3-pass hi/lo); scores already in exp2 domain ----
        #pragma unroll
        for (int kc = 0; kc < 4; kc++) {
            uint32_t aH[4], aL[4];
            ldmx4(aH[0], aH[1], aH[2], aH[3], smb + QH_OFF + a_off + kc * 32);
            ldmx4(aL[0], aL[1], aL[2], aL[3], smb + QL_OFF + a_off + kc * 32);
            #pragma unroll
            for (int np = 0; np < 4; np++) {
                uint32_t badr = (uint32_t)((np * 16 + ((bmat >> 1) << 3) + br8) * SK
                                           + kc * 16 + ((bmat & 1) << 3)) * 2;
                uint32_t bh0, bh1, bh2, bh3, bl0, bl1, bl2, bl3;
                ldmx4(bh0, bh1, bh2, bh3, KhB + badr);
                ldmx4(bl0, bl1, bl2, bl3, KlB + badr);
                mma16816(sacc[2 * np],     aH, bh0, bh1);
                mma16816(sacc[2 * np + 1], aH, bh2, bh3);
                mma16816(sacc[2 * np],     aH, bl0, bl1);
                mma16816(sacc[2 * np + 1], aH, bl2, bl3);
                mma16816(sacc[2 * np],     aL, bh0, bh1);
                mma16816(sacc[2 * np + 1], aL, bh2, bh3);
            }
        }

        // ---- mask (flagged fast path) + online softmax (exp2 domain) ----
        const int allm = ((const int*)(dynsm + FLAG_OFF))[kt];
        float mx0 = -1e30f, mx1 = -1e30f;
        if (allm) {
            #pragma unroll
            for (int f = 0; f < 8; f++) {
                mx0 = fmaxf(mx0, fmaxf(sacc[f][0], sacc[f][1]));
                mx1 = fmaxf(mx1, fmaxf(sacc[f][2], sacc[f][3]));
            }
        } else {
            const int* ms = (const int*)(dynsm + MS_OFF + buf * 256);
            #pragma unroll
            for (int f = 0; f < 8; f++) {
                int c0 = f * 8 + (l & 3) * 2;
                int mk0 = ms[c0], mk1 = ms[c0 + 1];
                float t0 = mk0 ? sacc[f][0] : -1e30f;
                float t1 = mk1 ? sacc[f][1] : -1e30f;
                float t2 = mk0 ? sacc[f][2] : -1e30f;
                float t3 = mk1 ? sacc[f][3] : -1e30f;
                sacc[f][0] = t0; sacc[f][1] = t1; sacc[f][2] = t2; sacc[f][3] = t3;
                mx0 = fmaxf(mx0, fmaxf(t0, t1));
                mx1 = fmaxf(mx1, fmaxf(t2, t3));
            }
        }
        mx0 = fmaxf(mx0, __shfl_xor_sync(0xffffffffu, mx0, 1));
        mx0 = fmaxf(mx0, __shfl_xor_sync(0xffffffffu, mx0, 2));
        mx1 = fmaxf(mx1, __shfl_xor_sync(0xffffffffu, mx1, 1));
        mx1 = fmaxf(mx1, __shfl_xor_sync(0xffffffffu, mx1, 2));
        float mn0 = fmaxf(mrun0, mx0), mn1 = fmaxf(mrun1, mx1);
        float cor0 = ex2f(mrun0 - mn0), cor1 = ex2f(mrun1 - mn1);
        mrun0 = mn0; mrun1 = mn1;
        float sum0 = 0.0f, sum1 = 0.0f;
        #pragma unroll
        for (int f = 0; f < 8; f++) {
            float p0 = ex2f(sacc[f][0] - mn0);
            float p1 = ex2f(sacc[f][1] - mn0);
            float p2 = ex2f(sacc[f][2] - mn1);
            float p3 = ex2f(sacc[f][3] - mn1);
            sacc[f][0] = p0; sacc[f][1] = p1; sacc[f][2] = p2; sacc[f][3] = p3;
            sum0 += p0 + p1; sum1 += p2 + p3;
        }
        sum0 += __shfl_xor_sync(0xffffffffu, sum0, 1);
        sum0 += __shfl_xor_sync(0xffffffffu, sum0, 2);
        sum1 += __shfl_xor_sync(0xffffffffu, sum1, 1);
        sum1 += __shfl_xor_sync(0xffffffffu, sum1, 2);
        lrun0 = lrun0 * cor0 + sum0;
        lrun1 = lrun1 * cor1 + sum1;
        #pragma unroll
        for (int nf = 0; nf < 8; nf++) {
            Oacc[nf][0] *= cor0; Oacc[nf][1] *= cor0;
            Oacc[nf][2] *= cor1; Oacc[nf][3] *= cor1;
        }

        // ---- O += P V (3-pass hi/lo) ----
        #pragma unroll
        for (int kc2 = 0; kc2 < 4; kc2++) {
            const float* f0 = sacc[2 * kc2];
            const float* f1 = sacc[2 * kc2 + 1];
            uint32_t aH2[4], aL2[4];
            aH2[0] = cvt2bf(f0[1], f0[0]);
            aH2[1] = cvt2bf(f0[3], f0[2]);
            aH2[2] = cvt2bf(f1[1], f1[0]);
            aH2[3] = cvt2bf(f1[3], f1[2]);
            aL2[0] = cvt2bf(f0[1] - bfhi(aH2[0]), f0[0] - bflo(aH2[0]));
            aL2[1] = cvt2bf(f0[3] - bfhi(aH2[1]), f0[2] - bflo(aH2[1]));
            aL2[2] = cvt2bf(f1[1] - bfhi(aH2[2]), f1[0] - bflo(aH2[2]));
            aL2[3] = cvt2bf(f1[3] - bfhi(aH2[3]), f1[2] - bflo(aH2[3]));
            #pragma unroll
            for (int nf = 0; nf < 4; nf++) {
                uint32_t vadr = (uint32_t)((kc2 * 16 + (l & 15)) * SK
                                           + nf * 16 + ((l >> 4) << 3)) * 2;
                uint32_t vh0, vh1, vh2, vh3, vl0, vl1, vl2, vl3;
                ldmx4t(vh0, vh1, vh2, vh3, VhB + vadr);
                ldmx4t(vl0, vl1, vl2, vl3, VlB + vadr);
                mma16816(Oacc[2 * nf],     aH2, vh0, vh1);
                mma16816(Oacc[2 * nf + 1], aH2, vh2, vh3);
                mma16816(Oacc[2 * nf],     aH2, vl0, vl1);
                mma16816(Oacc[2 * nf + 1], aH2, vl2, vl3);
                mma16816(Oacc[2 * nf],     aL2, vh0, vh1);
                mma16816(Oacc[2 * nf + 1], aL2, vh2, vh3);
            }
        }
        __syncthreads();
    }

    const float inv0 = 1.0f / lrun0;
    const float inv1 = 1.0f / lrun1;
    const int r0 = q0 + w * 16 + (l >> 2);
    #pragma unroll
    for (int nf = 0; nf < 8; nf++) {
        int col = hd + nf * 8 + (l & 3) * 2;
        float v0 = Oacc[nf][0] * inv0, v1 = Oacc[nf][1] * inv0;
        uint32_t ph = cvt2bf(v1, v0);
        uint32_t pl = cvt2bf(v1 - bfhi(ph), v0 - bflo(ph));
        *(uint32_t*)&cHi[(bS + r0) * D_ + col] = ph;
        *(uint32_t*)&cLo[(bS + r0) * D_ + col] = pl;
        float v2 = Oacc[nf][2] * inv1, v3 = Oacc[nf][3] * inv1;
        ph = cvt2bf(v3, v2);
        pl = cvt2bf(v3 - bfhi(ph), v2 - bflo(ph));
        *(uint32_t*)&cHi[(bS + r0 + 8) * D_ + col] = ph;
        *(uint32_t*)&cLo[(bS + r0 + 8) * D_ + col] = pl;
    }
}

// ---------------------------------------------------------------------------
extern "C" void kernel_launch(void* const* d_in, const int* in_sizes, int n_in,
                              void* d_out, int out_size)
{
    (void)in_sizes; (void)n_in; (void)out_size;
    const float* query = (const float*)d_in[0];
    const float* key   = (const float*)d_in[1];
    const float* value = (const float*)d_in[2];
    const int*   mask  = (const int*)d_in[3];
    const float* Wq = (const float*)d_in[4];
    const float* bq = (const float*)d_in[5];
    const float* Wk = (const float*)d_in[6];
    const float* bk = (const float*)d_in[7];
    const float* Wv = (const float*)d_in[8];
    const float* bv = (const float*)d_in[9];
    const float* Wo = (const float*)d_in[10];
    const float* bo = (const float*)d_in[11];
    float* out = (float*)d_out;

    __nv_bfloat16 *qh, *ql, *kh, *kl, *vh, *vl, *ch, *cl;
    __nv_bfloat16 *aqh, *aql, *akh, *akl, *avh, *avl;
    __nv_bfloat16 *wqh, *wql, *wkh, *wkl, *wvh, *wvl, *woh, *wol;
    cudaGetSymbolAddress((void**)&qh, g_qh);   cudaGetSymbolAddress((void**)&ql, g_ql);
    cudaGetSymbolAddress((void**)&kh, g_kh);   cudaGetSymbolAddress((void**)&kl, g_kl);
    cudaGetSymbolAddress((void**)&vh, g_vh);   cudaGetSymbolAddress((void**)&vl, g_vl);
    cudaGetSymbolAddress((void**)&ch, g_ch);   cudaGetSymbolAddress((void**)&cl, g_cl);
    cudaGetSymbolAddress((void**)&aqh, g_aqh); cudaGetSymbolAddress((void**)&aql, g_aql);
    cudaGetSymbolAddress((void**)&akh, g_akh); cudaGetSymbolAddress((void**)&akl, g_akl);
    cudaGetSymbolAddress((void**)&avh, g_avh); cudaGetSymbolAddress((void**)&avl, g_avl);
    cudaGetSymbolAddress((void**)&wqh, g_wqh); cudaGetSymbolAddress((void**)&wql, g_wql);
    cudaGetSymbolAddress((void**)&wkh, g_wkh); cudaGetSymbolAddress((void**)&wkl, g_wkl);
    cudaGetSymbolAddress((void**)&wvh, g_wvh); cudaGetSymbolAddress((void**)&wvl, g_wvl);
    cudaGetSymbolAddress((void**)&woh, g_woh); cudaGetSymbolAddress((void**)&wol, g_wol);

    const int actN4 = B_ * S_ * D_ / 4;
    const int wN4   = D_ * D_ / 4;
    const float SC2 = 0.18033688011112042f;   // 0.125 * log2(e)

    cudaFuncSetAttribute(gemm3<true>, cudaFuncAttributeMaxDynamicSharedMemorySize,
                         GEMM_SMEM);
    cudaFuncSetAttribute(gemm3<false>, cudaFuncAttributeMaxDynamicSharedMemorySize,
                         GEMM_SMEM);
    cudaFuncSetAttribute(attn_mma, cudaFuncAttributeMaxDynamicSharedMemorySize,
                         ATTN_SMEM);

    split_acts<<<dim3(actN4 / 256, 3), 256>>>(query, key, value,
                                              aqh, aql, akh, akl, avh, avl);
    split_weights<<<dim3(wN4 / 256, 4), 256>>>(Wq, Wk, Wv, Wo,
                                               wqh, wql, wkh, wkl,
                                               wvh, wvl, woh, wol);

    // Fused Q/K/V projections; Q pre-scaled into exp2 domain
    dim3 ggrid(D_ / BN, (B_ * S_) / BM, 3);
    gemm3<true><<<ggrid, 256, GEMM_SMEM>>>(
        aqh, aql, wqh, wql, bq,
        akh, akl, wkh, wkl, bk,
        avh, avl, wvh, wvl, bv,
        SC2, 1.0f, 1.0f,
        nullptr, qh, ql, kh, kl, vh, vl);

    dim3 agrid(S_ / 128, H_, B_);
    attn_mma<<<agrid, 256, ATTN_SMEM>>>(qh, ql, kh, kl, vh, vl, mask, ch, cl);

    dim3 ogrid(D_ / BN, (B_ * S_) / BM, 1);
    gemm3<false><<<ogrid, 256, GEMM_SMEM>>>(
        ch, cl, woh, wol, bo,
        ch, cl, woh, wol, bo,
        ch, cl, woh, wol, bo,
        1.0f, 1.0f, 1.0f,
        out, nullptr, nullptr, nullptr, nullptr, nullptr, nullptr);
}

// round 10
// speedup vs baseline: 1.1689x; 1.1288x over previous
#include <cuda_runtime.h>
#include <cuda_bf16.h>
#include <math.h>
#include <stdint.h>

// Problem constants
#define B_  2
#define S_  2048
#define D_  1024
#define H_  16
#define DK_ 64

// GEMM tiling (tf32): 128x128 tile, 256 threads, 2-stage, 2 CTAs/SM
#define BM 128
#define BN 128
#define BK 32
#define KDIM 1024
#define CHUNKS 32
#define RS 36                            // fp32 row stride (bank-conflict-free)
#define A_T (128 * RS * 4)               // 18432 B
#define B_T (128 * RS * 4)
#define BUF (A_T + B_T)                  // 36864
#define GEMM_SMEM (2 * BUF)              // 73728

// Attention smem layout (64-key tiles, 2 CTAs/SM) — unchanged from R9
#define SK 72
#define QT_B (128 * SK * 2)
#define KT_B (64 * SK * 2)
#define QH_OFF 0
#define QL_OFF QT_B
#define KV_OFF(buf, t) (2 * QT_B + (buf) * 4 * KT_B + (t) * KT_B)
#define MS_OFF (2 * QT_B + 8 * KT_B)
#define FLAG_OFF (MS_OFF + 512)
#define ATTN_SMEM (FLAG_OFF + 128)

// Scratch (device globals)
__device__ __nv_bfloat16 g_qh[B_*S_*D_], g_ql[B_*S_*D_];
__device__ __nv_bfloat16 g_kh[B_*S_*D_], g_kl[B_*S_*D_];
__device__ __nv_bfloat16 g_vh[B_*S_*D_], g_vl[B_*S_*D_];
__device__ float g_rq[B_*S_*D_], g_rk[B_*S_*D_], g_rv[B_*S_*D_];
__device__ float g_ctx[B_*S_*D_];
__device__ float g_rwq[D_*D_], g_rwk[D_*D_], g_rwv[D_*D_], g_rwo[D_*D_];

// ===========================================================================
// Helpers
// ===========================================================================
__device__ __forceinline__ uint32_t smem_u32(const void* p) {
    uint32_t a;
    asm("{ .reg .u64 t; cvta.to.shared.u64 t, %1; cvt.u32.u64 %0, t; }"
        : "=r"(a) : "l"(p));
    return a;
}
__device__ __forceinline__ void cp16(uint32_t dst, const void* src) {
    asm volatile("cp.async.cg.shared.global [%0], [%1], 16;" :: "r"(dst), "l"(src));
}
__device__ __forceinline__ void cp4(uint32_t dst, const void* src) {
    asm volatile("cp.async.ca.shared.global [%0], [%1], 4;" :: "r"(dst), "l"(src));
}
__device__ __forceinline__ void ldmx4(uint32_t& r0, uint32_t& r1,
                                      uint32_t& r2, uint32_t& r3, uint32_t addr) {
    asm volatile("ldmatrix.sync.aligned.m8n8.x4.shared.b16 {%0,%1,%2,%3}, [%4];"
                 : "=r"(r0), "=r"(r1), "=r"(r2), "=r"(r3) : "r"(addr));
}
__device__ __forceinline__ void ldmx4t(uint32_t& r0, uint32_t& r1,
                                       uint32_t& r2, uint32_t& r3, uint32_t addr) {
    asm volatile("ldmatrix.sync.aligned.m8n8.x4.trans.shared.b16 {%0,%1,%2,%3}, [%4];"
                 : "=r"(r0), "=r"(r1), "=r"(r2), "=r"(r3) : "r"(addr));
}
__device__ __forceinline__ void mma16816(float* c, const uint32_t* a,
                                         uint32_t b0, uint32_t b1) {
    asm volatile(
        "mma.sync.aligned.m16n8k16.row.col.f32.bf16.bf16.f32 "
        "{%0,%1,%2,%3}, {%4,%5,%6,%7}, {%8,%9}, {%0,%1,%2,%3};"
        : "+f"(c[0]), "+f"(c[1]), "+f"(c[2]), "+f"(c[3])
        : "r"(a[0]), "r"(a[1]), "r"(a[2]), "r"(a[3]), "r"(b0), "r"(b1));
}
__device__ __forceinline__ void mma_tf32(float* c, const uint32_t* a,
                                         uint32_t b0, uint32_t b1) {
    asm volatile(
        "mma.sync.aligned.m16n8k8.row.col.f32.tf32.tf32.f32 "
        "{%0,%1,%2,%3}, {%4,%5,%6,%7}, {%8,%9}, {%0,%1,%2,%3};"
        : "+f"(c[0]), "+f"(c[1]), "+f"(c[2]), "+f"(c[3])
        : "r"(a[0]), "r"(a[1]), "r"(a[2]), "r"(a[3]), "r"(b0), "r"(b1));
}
__device__ __forceinline__ uint32_t cvt2bf(float hi_elem, float lo_elem) {
    uint32_t r;
    asm("cvt.rn.bf16x2.f32 %0, %1, %2;" : "=r"(r) : "f"(hi_elem), "f"(lo_elem));
    return r;
}
__device__ __forceinline__ float bflo(uint32_t p) { return __uint_as_float(p << 16); }
__device__ __forceinline__ float bfhi(uint32_t p) { return __uint_as_float(p & 0xFFFF0000u); }
__device__ __forceinline__ float ex2f(float x) {
    float y; asm("ex2.approx.f32 %0, %1;" : "=f"(y) : "f"(x)); return y;
}
__device__ __forceinline__ float tf32r(float x) {
    float y; asm("cvt.rna.tf32.f32 %0, %1;" : "=f"(y) : "f"(x)); return y;
}

// ===========================================================================
// Rounding kernels: fp32 -> tf32-rounded fp32 (batched)
// ===========================================================================
__device__ __forceinline__ void round_one(const float* x, float* r, int i) {
    float4 v = ((const float4*)x)[i];
    v.x = tf32r(v.x); v.y = tf32r(v.y); v.z = tf32r(v.z); v.w = tf32r(v.w);
    ((float4*)r)[i] = v;
}

__global__ __launch_bounds__(256) void round_acts(
    const float* __restrict__ q, const float* __restrict__ k,
    const float* __restrict__ v,
    float* rq, float* rk, float* rv)
{
    int i = blockIdx.x * 256 + threadIdx.x;
    int z = blockIdx.y;
    const float* x = (z == 0) ? q : (z == 1) ? k : v;
    float* r = (z == 0) ? rq : (z == 1) ? rk : rv;
    round_one(x, r, i);
}

__global__ __launch_bounds__(256) void round_weights(
    const float* __restrict__ w0, const float* __restrict__ w1,
    const float* __restrict__ w2, const float* __restrict__ w3,
    float* r0, float* r1, float* r2, float* r3)
{
    int i = blockIdx.x * 256 + threadIdx.x;
    int z = blockIdx.y;
    const float* x = (z == 0) ? w0 : (z == 1) ? w1 : (z == 2) ? w2 : w3;
    float* r = (z == 0) ? r0 : (z == 1) ? r1 : (z == 2) ? r2 : r3;
    round_one(x, r, i);
}

// ===========================================================================
// TF32 GEMM (NT + bias, optional output scale): 128x128, 256 thr, 2 CTAs/SM.
// Single-pass tf32 mma (inputs pre-rounded with cvt.rna).
// SPLIT=true -> bf16 hi/lo outputs (Q/K/V); false -> fp32 output.
// ===========================================================================
template<bool SPLIT>
__global__ __launch_bounds__(256, 2) void gemm_tf32(
    const float* __restrict__ a0, const float* __restrict__ w0,
    const float* __restrict__ bias0,
    const float* __restrict__ a1, const float* __restrict__ w1,
    const float* __restrict__ bias1,
    const float* __restrict__ a2, const float* __restrict__ w2,
    const float* __restrict__ bias2,
    float s0, float s1, float s2,
    float* __restrict__ Cf,
    __nv_bfloat16* __restrict__ C0h, __nv_bfloat16* __restrict__ C0l,
    __nv_bfloat16* __restrict__ C1h, __nv_bfloat16* __restrict__ C1l,
    __nv_bfloat16* __restrict__ C2h, __nv_bfloat16* __restrict__ C2l)
{
    extern __shared__ char dynsm[];
    const uint32_t smb = smem_u32(dynsm);
    const int tid = threadIdx.x;
    const int l = tid & 31;
    const int wid = tid >> 5;
    const int wm = (wid & 3) * 32;
    const int wn = (wid >> 2) * 64;
    const int bm = blockIdx.y * BM;
    const int bn = blockIdx.x * BN;
    const int z = blockIdx.z;

    const float* A = (z == 0) ? a0 : (z == 1) ? a1 : a2;
    const float* W = (z == 0) ? w0 : (z == 1) ? w1 : w2;
    const float* bias = (z == 0) ? bias0 : (z == 1) ? bias1 : bias2;
    const float osc = (z == 0) ? s0 : (z == 1) ? s1 : s2;
    __nv_bfloat16* Chi = (z == 0) ? C0h : (z == 1) ? C1h : C2h;
    __nv_bfloat16* Clo = (z == 0) ? C0l : (z == 1) ? C1l : C2l;

    float acc[2][8][4];
    #pragma unroll
    for (int mi = 0; mi < 2; mi++)
        #pragma unroll
        for (int nj = 0; nj < 8; nj++)
            #pragma unroll
            for (int q = 0; q < 4; q++) acc[mi][nj][q] = 0.0f;

    auto issue = [&](int c, int buf) {
        const int kk = c * BK;
        const uint32_t base = smb + buf * BUF;
        #pragma unroll
        for (int i = 0; i < 4; i++) {
            int idx = tid + i * 256;          // 0..1023
            int row = idx >> 3, s4 = (idx & 7) * 4;
            uint32_t off = (uint32_t)(row * RS + s4) * 4;
            cp16(base + off,       A + (size_t)(bm + row) * KDIM + kk + s4);
            cp16(base + A_T + off, W + (size_t)(bn + row) * KDIM + kk + s4);
        }
        asm volatile("cp.async.commit_group;" ::: "memory");
    };

    // Quadrant row/col for tf32 fragment via ldmatrix-b16 trick
    const int qrow = (l & 7) + ((l >> 3) & 1) * 8;
    const int qcol = (l >> 4) * 4;

    auto compute = [&](int buf) {
        const uint32_t aB = smb + buf * BUF;
        const uint32_t bB = aB + A_T;
        #pragma unroll
        for (int k8 = 0; k8 < 4; k8++) {
            uint32_t a[2][4];
            #pragma unroll
            for (int mi = 0; mi < 2; mi++) {
                uint32_t addr = aB + (uint32_t)((wm + mi * 16 + qrow) * RS
                                                + k8 * 8 + qcol) * 4;
                ldmx4(a[mi][0], a[mi][1], a[mi][2], a[mi][3], addr);
            }
            uint32_t b[4][4];
            #pragma unroll
            for (int p = 0; p < 4; p++) {
                uint32_t addr = bB + (uint32_t)((wn + p * 16 + qrow) * RS
                                                + k8 * 8 + qcol) * 4;
                ldmx4(b[p][0], b[p][1], b[p][2], b[p][3], addr);
            }
            #pragma unroll
            for (int p = 0; p < 4; p++) {
                #pragma unroll
                for (int mi = 0; mi < 2; mi++) {
                    mma_tf32(acc[mi][2 * p],     a[mi], b[p][0], b[p][2]);
                    mma_tf32(acc[mi][2 * p + 1], a[mi], b[p][1], b[p][3]);
                }
            }
        }
    };

    issue(0, 0);
    for (int c = 0; c < CHUNKS; ++c) {
        if (c + 1 < CHUNKS) {
            issue(c + 1, (c + 1) & 1);
            asm volatile("cp.async.wait_group 1;" ::: "memory");
        } else {
            asm volatile("cp.async.wait_group 0;" ::: "memory");
        }
        __syncthreads();
        compute(c & 1);
        __syncthreads();
    }

    #pragma unroll
    for (int mi = 0; mi < 2; mi++) {
        int r0 = bm + wm + mi * 16 + (l >> 2);
        #pragma unroll
        for (int nj = 0; nj < 8; nj++) {
            int col = bn + wn + nj * 8 + (l & 3) * 2;
            float2 bv = *(const float2*)&bias[col];
            float v0 = (acc[mi][nj][0] + bv.x) * osc;
            float v1 = (acc[mi][nj][1] + bv.y) * osc;
            float v2 = (acc[mi][nj][2] + bv.x) * osc;
            float v3 = (acc[mi][nj][3] + bv.y) * osc;
            if (SPLIT) {
                uint32_t ph = cvt2bf(v1, v0);
                uint32_t pl = cvt2bf(v1 - bfhi(ph), v0 - bflo(ph));
                *(uint32_t*)&Chi[(size_t)r0 * D_ + col] = ph;
                *(uint32_t*)&Clo[(size_t)r0 * D_ + col] = pl;
                ph = cvt2bf(v3, v2);
                pl = cvt2bf(v3 - bfhi(ph), v2 - bflo(ph));
                *(uint32_t*)&Chi[(size_t)(r0 + 8) * D_ + col] = ph;
                *(uint32_t*)&Clo[(size_t)(r0 + 8) * D_ + col] = pl;
            } else {
                *(float2*)&Cf[(size_t)r0 * D_ + col] = make_float2(v0, v1);
                *(float2*)&Cf[(size_t)(r0 + 8) * D_ + col] = make_float2(v2, v3);
            }
        }
    }
}

// ===========================================================================
// Tensor-core flash attention (bf16 hi/lo, exp2-domain softmax) — R9 version.
// Epilogue writes tf32-rounded fp32 ctx (consumed by tf32 out-proj).
// ===========================================================================
__global__ __launch_bounds__(256, 2) void attn_mma(
    const __nv_bfloat16* __restrict__ qHi, const __nv_bfloat16* __restrict__ qLo,
    const __nv_bfloat16* __restrict__ kHi, const __nv_bfloat16* __restrict__ kLo,
    const __nv_bfloat16* __restrict__ vHi, const __nv_bfloat16* __restrict__ vLo,
    const int* __restrict__ mask,
    float* __restrict__ ctx)
{
    extern __shared__ char dynsm[];
    const uint32_t smb = smem_u32(dynsm);
    const int tid = threadIdx.x;
    const int w = tid >> 5, l = tid & 31;
    const int b = blockIdx.z, h = blockIdx.y;
    const int q0 = blockIdx.x * 128;
    const size_t bS = (size_t)b * S_;
    const int hd = h * DK_;

    // Per-tile all-ones flags
    {
        const int4* mp = (const int4*)(mask + b * S_);
        int4 a = mp[tid * 2];
        int4 c = mp[tid * 2 + 1];
        int allm = a.x & a.y & a.z & a.w & c.x & c.y & c.z & c.w;
        allm &= __shfl_xor_sync(0xffffffffu, allm, 1);
        allm &= __shfl_xor_sync(0xffffffffu, allm, 2);
        allm &= __shfl_xor_sync(0xffffffffu, allm, 4);
        if ((tid & 7) == 0)
            ((int*)(dynsm + FLAG_OFF))[tid >> 3] = allm;
    }

    auto load_q = [&](const __nv_bfloat16* g, uint32_t off) {
        #pragma unroll
        for (int t = 0; t < 4; t++) {
            int idx = tid + t * 256;
            int row = idx >> 3, seg = (idx & 7) * 8;
            cp16(smb + off + (uint32_t)(row * SK + seg) * 2,
                 g + (bS + q0 + row) * D_ + hd + seg);
        }
    };
    auto load_kv_tile = [&](const __nv_bfloat16* g, uint32_t off, int tok0) {
        #pragma unroll
        for (int t = 0; t < 2; t++) {
            int idx = tid + t * 256;
            int row = idx >> 3, seg = (idx & 7) * 8;
            cp16(smb + off + (uint32_t)(row * SK + seg) * 2,
                 g + (bS + tok0 + row) * D_ + hd + seg);
        }
    };
    auto load_kv = [&](int kt, int buf) {
        int tok0 = kt * 64;
        load_kv_tile(kHi, KV_OFF(buf, 0), tok0);
        load_kv_tile(kLo, KV_OFF(buf, 1), tok0);
        load_kv_tile(vHi, KV_OFF(buf, 2), tok0);
        load_kv_tile(vLo, KV_OFF(buf, 3), tok0);
        if (tid < 64) cp4(smb + MS_OFF + (uint32_t)(buf * 64 + tid) * 4,
                          mask + b * S_ + tok0 + tid);
    };

    load_q(qHi, QH_OFF);
    load_q(qLo, QL_OFF);
    load_kv(0, 0);
    asm volatile("cp.async.commit_group;" ::: "memory");

    float Oacc[8][4];
    #pragma unroll
    for (int nf = 0; nf < 8; nf++)
        #pragma unroll
        for (int q = 0; q < 4; q++) Oacc[nf][q] = 0.0f;
    float mrun0 = -1e30f, mrun1 = -1e30f, lrun0 = 0.0f, lrun1 = 0.0f;

    const uint32_t a_off = (uint32_t)((w * 16 + (l & 15)) * SK + ((l >> 4) << 3)) * 2;
    const int bmat = l >> 3, br8 = l & 7;

    for (int kt = 0; kt < 32; kt++) {
        const int buf = kt & 1;
        if (kt < 31) {
            load_kv(kt + 1, buf ^ 1);
            asm volatile("cp.async.commit_group;" ::: "memory");
            asm volatile("cp.async.wait_group 1;" ::: "memory");
        } else {
            asm volatile("cp.async.wait_group 0;" ::: "memory");
        }
        __syncthreads();

        const uint32_t KhB = smb + KV_OFF(buf, 0), KlB = smb + KV_OFF(buf, 1);
        const uint32_t VhB = smb + KV_OFF(buf, 2), VlB = smb + KV_OFF(buf, 3);

        float sacc[8][4];
        #pragma unroll
        for (int f = 0; f < 8; f++)
            #pragma unroll
            for (int q = 0; q < 4; q++) sacc[f][q] = 0.0f;

        #pragma unroll
        for (int kc = 0; kc < 4; kc++) {
            uint32_t aH[4], aL[4];
            ldmx4(aH[0], aH[1], aH[2], aH[3], smb + QH_OFF + a_off + kc * 32);
            ldmx4(aL[0], aL[1], aL[2], aL[3], smb + QL_OFF + a_off + kc * 32);
            #pragma unroll
            for (int np = 0; np < 4; np++) {
                uint32_t badr = (uint32_t)((np * 16 + ((bmat >> 1) << 3) + br8) * SK
                                           + kc * 16 + ((bmat & 1) << 3)) * 2;
                uint32_t bh0, bh1, bh2, bh3, bl0, bl1, bl2, bl3;
                ldmx4(bh0, bh1, bh2, bh3, KhB + badr);
                ldmx4(bl0, bl1, bl2, bl3, KlB + badr);
                mma16816(sacc[2 * np],     aH, bh0, bh1);
                mma16816(sacc[2 * np + 1], aH, bh2, bh3);
                mma16816(sacc[2 * np],     aH, bl0, bl1);
                mma16816(sacc[2 * np + 1], aH, bl2, bl3);
                mma16816(sacc[2 * np],     aL, bh0, bh1);
                mma16816(sacc[2 * np + 1], aL, bh2, bh3);
            }
        }

        const int allm = ((const int*)(dynsm + FLAG_OFF))[kt];
        float mx0 = -1e30f, mx1 = -1e30f;
        if (allm) {
            #pragma unroll
            for (int f = 0; f < 8; f++) {
                mx0 = fmaxf(mx0, fmaxf(sacc[f][0], sacc[f][1]));
                mx1 = fmaxf(mx1, fmaxf(sacc[f][2], sacc[f][3]));
            }
        } else {
            const int* ms = (const int*)(dynsm + MS_OFF + buf * 256);
            #pragma unroll
            for (int f = 0; f < 8; f++) {
                int c0 = f * 8 + (l & 3) * 2;
                int mk0 = ms[c0], mk1 = ms[c0 + 1];
                float t0 = mk0 ? sacc[f][0] : -1e30f;
                float t1 = mk1 ? sacc[f][1] : -1e30f;
                float t2 = mk0 ? sacc[f][2] : -1e30f;
                float t3 = mk1 ? sacc[f][3] : -1e30f;
                sacc[f][0] = t0; sacc[f][1] = t1; sacc[f][2] = t2; sacc[f][3] = t3;
                mx0 = fmaxf(mx0, fmaxf(t0, t1));
                mx1 = fmaxf(mx1, fmaxf(t2, t3));
            }
        }
        mx0 = fmaxf(mx0, __shfl_xor_sync(0xffffffffu, mx0, 1));
        mx0 = fmaxf(mx0, __shfl_xor_sync(0xffffffffu, mx0, 2));
        mx1 = fmaxf(mx1, __shfl_xor_sync(0xffffffffu, mx1, 1));
        mx1 = fmaxf(mx1, __shfl_xor_sync(0xffffffffu, mx1, 2));
        float mn0 = fmaxf(mrun0, mx0), mn1 = fmaxf(mrun1, mx1);
        float cor0 = ex2f(mrun0 - mn0), cor1 = ex2f(mrun1 - mn1);
        mrun0 = mn0; mrun1 = mn1;
        float sum0 = 0.0f, sum1 = 0.0f;
        #pragma unroll
        for (int f = 0; f < 8; f++) {
            float p0 = ex2f(sacc[f][0] - mn0);
            float p1 = ex2f(sacc[f][1] - mn0);
            float p2 = ex2f(sacc[f][2] - mn1);
            float p3 = ex2f(sacc[f][3] - mn1);
            sacc[f][0] = p0; sacc[f][1] = p1; sacc[f][2] = p2; sacc[f][3] = p3;
            sum0 += p0 + p1; sum1 += p2 + p3;
        }
        sum0 += __shfl_xor_sync(0xffffffffu, sum0, 1);
        sum0 += __shfl_xor_sync(0xffffffffu, sum0, 2);
        sum1 += __shfl_xor_sync(0xffffffffu, sum1, 1);
        sum1 += __shfl_xor_sync(0xffffffffu, sum1, 2);
        lrun0 = lrun0 * cor0 + sum0;
        lrun1 = lrun1 * cor1 + sum1;
        #pragma unroll
        for (int nf = 0; nf < 8; nf++) {
            Oacc[nf][0] *= cor0; Oacc[nf][1] *= cor0;
            Oacc[nf][2] *= cor1; Oacc[nf][3] *= cor1;
        }

        #pragma unroll
        for (int kc2 = 0; kc2 < 4; kc2++) {
            const float* f0 = sacc[2 * kc2];
            const float* f1 = sacc[2 * kc2 + 1];
            uint32_t aH2[4], aL2[4];
            aH2[0] = cvt2bf(f0[1], f0[0]);
            aH2[1] = cvt2bf(f0[3], f0[2]);
            aH2[2] = cvt2bf(f1[1], f1[0]);
            aH2[3] = cvt2bf(f1[3], f1[2]);
            aL2[0] = cvt2bf(f0[1] - bfhi(aH2[0]), f0[0] - bflo(aH2[0]));
            aL2[1] = cvt2bf(f0[3] - bfhi(aH2[1]), f0[2] - bflo(aH2[1]));
            aL2[2] = cvt2bf(f1[1] - bfhi(aH2[2]), f1[0] - bflo(aH2[2]));
            aL2[3] = cvt2bf(f1[3] - bfhi(aH2[3]), f1[2] - bflo(aH2[3]));
            #pragma unroll
            for (int nf = 0; nf < 4; nf++) {
                uint32_t vadr = (uint32_t)((kc2 * 16 + (l & 15)) * SK
                                           + nf * 16 + ((l >> 4) << 3)) * 2;
                uint32_t vh0, vh1, vh2, vh3, vl0, vl1, vl2, vl3;
                ldmx4t(vh0, vh1, vh2, vh3, VhB + vadr);
                ldmx4t(vl0, vl1, vl2, vl3, VlB + vadr);
                mma16816(Oacc[2 * nf],     aH2, vh0, vh1);
                mma16816(Oacc[2 * nf + 1], aH2, vh2, vh3);
                mma16816(Oacc[2 * nf],     aH2, vl0, vl1);
                mma16816(Oacc[2 * nf + 1], aH2, vl2, vl3);
                mma16816(Oacc[2 * nf],     aL2, vh0, vh1);
                mma16816(Oacc[2 * nf + 1], aL2, vh2, vh3);
            }
        }
        __syncthreads();
    }

    // Epilogue: normalize, tf32-round, write fp32 ctx
    const float inv0 = 1.0f / lrun0;
    const float inv1 = 1.0f / lrun1;
    const int r0 = q0 + w * 16 + (l >> 2);
    #pragma unroll
    for (int nf = 0; nf < 8; nf++) {
        int col = hd + nf * 8 + (l & 3) * 2;
        float2 o0, o1;
        o0.x = tf32r(Oacc[nf][0] * inv0);
        o0.y = tf32r(Oacc[nf][1] * inv0);
        o1.x = tf32r(Oacc[nf][2] * inv1);
        o1.y = tf32r(Oacc[nf][3] * inv1);
        *(float2*)&ctx[(bS + r0) * D_ + col] = o0;
        *(float2*)&ctx[(bS + r0 + 8) * D_ + col] = o1;
    }
}

// ---------------------------------------------------------------------------
extern "C" void kernel_launch(void* const* d_in, const int* in_sizes, int n_in,
                              void* d_out, int out_size)
{
    (void)in_sizes; (void)n_in; (void)out_size;
    const float* query = (const float*)d_in[0];
    const float* key   = (const float*)d_in[1];
    const float* value = (const float*)d_in[2];
    const int*   mask  = (const int*)d_in[3];
    const float* Wq = (const float*)d_in[4];
    const float* bq = (const float*)d_in[5];
    const float* Wk = (const float*)d_in[6];
    const float* bk = (const float*)d_in[7];
    const float* Wv = (const float*)d_in[8];
    const float* bv = (const float*)d_in[9];
    const float* Wo = (const float*)d_in[10];
    const float* bo = (const float*)d_in[11];
    float* out = (float*)d_out;

    __nv_bfloat16 *qh, *ql, *kh, *kl, *vh, *vl;
    float *rq, *rk, *rv, *ctx, *rwq, *rwk, *rwv, *rwo;
    cudaGetSymbolAddress((void**)&qh, g_qh);   cudaGetSymbolAddress((void**)&ql, g_ql);
    cudaGetSymbolAddress((void**)&kh, g_kh);   cudaGetSymbolAddress((void**)&kl, g_kl);
    cudaGetSymbolAddress((void**)&vh, g_vh);   cudaGetSymbolAddress((void**)&vl, g_vl);
    cudaGetSymbolAddress((void**)&rq, g_rq);   cudaGetSymbolAddress((void**)&rk, g_rk);
    cudaGetSymbolAddress((void**)&rv, g_rv);   cudaGetSymbolAddress((void**)&ctx, g_ctx);
    cudaGetSymbolAddress((void**)&rwq, g_rwq); cudaGetSymbolAddress((void**)&rwk, g_rwk);
    cudaGetSymbolAddress((void**)&rwv, g_rwv); cudaGetSymbolAddress((void**)&rwo, g_rwo);

    const int actN4 = B_ * S_ * D_ / 4;
    const int wN4   = D_ * D_ / 4;
    const float SC2 = 0.18033688011112042f;   // 0.125 * log2(e)

    cudaFuncSetAttribute(gemm_tf32<true>, cudaFuncAttributeMaxDynamicSharedMemorySize,
                         GEMM_SMEM);
    cudaFuncSetAttribute(gemm_tf32<false>, cudaFuncAttributeMaxDynamicSharedMemorySize,
                         GEMM_SMEM);
    cudaFuncSetAttribute(attn_mma, cudaFuncAttributeMaxDynamicSharedMemorySize,
                         ATTN_SMEM);

    // tf32 rounding passes
    round_acts<<<dim3(actN4 / 256, 3), 256>>>(query, key, value, rq, rk, rv);
    round_weights<<<dim3(wN4 / 256, 4), 256>>>(Wq, Wk, Wv, Wo, rwq, rwk, rwv, rwo);

    // Fused Q/K/V projections (tf32 single-pass); Q pre-scaled into exp2 domain
    dim3 ggrid(D_ / BN, (B_ * S_) / BM, 3);
    gemm_tf32<true><<<ggrid, 256, GEMM_SMEM>>>(
        rq, rwq, bq,
        rk, rwk, bk,
        rv, rwv, bv,
        SC2, 1.0f, 1.0f,
        nullptr, qh, ql, kh, kl, vh, vl);

    // Attention (bf16 hi/lo, unchanged) -> tf32-rounded fp32 ctx
    dim3 agrid(S_ / 128, H_, B_);
    attn_mma<<<agrid, 256, ATTN_SMEM>>>(qh, ql, kh, kl, vh, vl, mask, ctx);

    // Output projection (tf32 single-pass, fp32 out)
    dim3 ogrid(D_ / BN, (B_ * S_) / BM, 1);
    gemm_tf32<false><<<ogrid, 256, GEMM_SMEM>>>(
        ctx, rwo, bo,
        ctx, rwo, bo,
        ctx, rwo, bo,
        1.0f, 1.0f, 1.0f,
        out, nullptr, nullptr, nullptr, nullptr, nullptr, nullptr);
}

// round 11
// speedup vs baseline: 1.1738x; 1.0041x over previous
#include <cuda_runtime.h>
#include <cuda_bf16.h>
#include <math.h>
#include <stdint.h>

// Problem constants
#define B_  2
#define S_  2048
#define D_  1024
#define H_  16
#define DK_ 64

// GEMM tiling (tf32): 128x128 tile, 256 threads, 3-stage, 2 CTAs/SM
#define BM 128
#define BN 128
#define BK 32
#define KDIM 1024
#define CHUNKS 32
#define RS 36                            // fp32 row stride (bank-conflict-free)
#define A_T (128 * RS * 4)               // 18432 B
#define B_T (128 * RS * 4)
#define BUF (A_T + B_T)                  // 36864
#define GEMM_SMEM (3 * BUF)              // 110592

// Attention smem layout (64-key tiles, 2 CTAs/SM)
#define SK 72
#define QT_B (128 * SK * 2)
#define KT_B (64 * SK * 2)
#define QH_OFF 0
#define QL_OFF QT_B
#define KV_OFF(buf, t) (2 * QT_B + (buf) * 4 * KT_B + (t) * KT_B)
#define MS_OFF (2 * QT_B + 8 * KT_B)
#define FLAG_OFF (MS_OFF + 512)
#define ATTN_SMEM (FLAG_OFF + 128)

// Scratch (device globals)
__device__ __nv_bfloat16 g_qh[B_*S_*D_], g_ql[B_*S_*D_];
__device__ __nv_bfloat16 g_kh[B_*S_*D_], g_kl[B_*S_*D_];
__device__ __nv_bfloat16 g_vh[B_*S_*D_], g_vl[B_*S_*D_];
__device__ float g_ctx[B_*S_*D_];

// ===========================================================================
// Helpers
// ===========================================================================
__device__ __forceinline__ uint32_t smem_u32(const void* p) {
    uint32_t a;
    asm("{ .reg .u64 t; cvta.to.shared.u64 t, %1; cvt.u32.u64 %0, t; }"
        : "=r"(a) : "l"(p));
    return a;
}
__device__ __forceinline__ void cp16(uint32_t dst, const void* src) {
    asm volatile("cp.async.cg.shared.global [%0], [%1], 16;" :: "r"(dst), "l"(src));
}
__device__ __forceinline__ void cp4(uint32_t dst, const void* src) {
    asm volatile("cp.async.ca.shared.global [%0], [%1], 4;" :: "r"(dst), "l"(src));
}
__device__ __forceinline__ void ldmx4(uint32_t& r0, uint32_t& r1,
                                      uint32_t& r2, uint32_t& r3, uint32_t addr) {
    asm volatile("ldmatrix.sync.aligned.m8n8.x4.shared.b16 {%0,%1,%2,%3}, [%4];"
                 : "=r"(r0), "=r"(r1), "=r"(r2), "=r"(r3) : "r"(addr));
}
__device__ __forceinline__ void ldmx4t(uint32_t& r0, uint32_t& r1,
                                       uint32_t& r2, uint32_t& r3, uint32_t addr) {
    asm volatile("ldmatrix.sync.aligned.m8n8.x4.trans.shared.b16 {%0,%1,%2,%3}, [%4];"
                 : "=r"(r0), "=r"(r1), "=r"(r2), "=r"(r3) : "r"(addr));
}
__device__ __forceinline__ void mma16816(float* c, const uint32_t* a,
                                         uint32_t b0, uint32_t b1) {
    asm volatile(
        "mma.sync.aligned.m16n8k16.row.col.f32.bf16.bf16.f32 "
        "{%0,%1,%2,%3}, {%4,%5,%6,%7}, {%8,%9}, {%0,%1,%2,%3};"
        : "+f"(c[0]), "+f"(c[1]), "+f"(c[2]), "+f"(c[3])
        : "r"(a[0]), "r"(a[1]), "r"(a[2]), "r"(a[3]), "r"(b0), "r"(b1));
}
__device__ __forceinline__ void mma_tf32(float* c, const uint32_t* a,
                                         uint32_t b0, uint32_t b1) {
    asm volatile(
        "mma.sync.aligned.m16n8k8.row.col.f32.tf32.tf32.f32 "
        "{%0,%1,%2,%3}, {%4,%5,%6,%7}, {%8,%9}, {%0,%1,%2,%3};"
        : "+f"(c[0]), "+f"(c[1]), "+f"(c[2]), "+f"(c[3])
        : "r"(a[0]), "r"(a[1]), "r"(a[2]), "r"(a[3]), "r"(b0), "r"(b1));
}
__device__ __forceinline__ uint32_t cvt2bf(float hi_elem, float lo_elem) {
    uint32_t r;
    asm("cvt.rn.bf16x2.f32 %0, %1, %2;" : "=r"(r) : "f"(hi_elem), "f"(lo_elem));
    return r;
}
__device__ __forceinline__ float bflo(uint32_t p) { return __uint_as_float(p << 16); }
__device__ __forceinline__ float bfhi(uint32_t p) { return __uint_as_float(p & 0xFFFF0000u); }
__device__ __forceinline__ float ex2f(float x) {
    float y; asm("ex2.approx.f32 %0, %1;" : "=f"(y) : "f"(x)); return y;
}
__device__ __forceinline__ uint32_t tf32u(uint32_t x) {
    float y;
    asm("cvt.rna.tf32.f32 %0, %1;" : "=f"(y) : "f"(__uint_as_float(x)));
    return __float_as_uint(y);
}

// ===========================================================================
// TF32 GEMM (NT + bias, optional output scale): 128x128, 256 thr, 2 CTAs/SM.
// Raw fp32 inputs; fragments rounded to tf32 (cvt.rna) in registers.
// 3-stage cp.async pipeline. SPLIT -> bf16 hi/lo outputs; else fp32.
// ===========================================================================
template<bool SPLIT>
__global__ __launch_bounds__(256, 2) void gemm_tf32(
    const float* __restrict__ a0, const float* __restrict__ w0,
    const float* __restrict__ bias0,
    const float* __restrict__ a1, const float* __restrict__ w1,
    const float* __restrict__ bias1,
    const float* __restrict__ a2, const float* __restrict__ w2,
    const float* __restrict__ bias2,
    float s0, float s1, float s2,
    float* __restrict__ Cf,
    __nv_bfloat16* __restrict__ C0h, __nv_bfloat16* __restrict__ C0l,
    __nv_bfloat16* __restrict__ C1h, __nv_bfloat16* __restrict__ C1l,
    __nv_bfloat16* __restrict__ C2h, __nv_bfloat16* __restrict__ C2l)
{
    extern __shared__ char dynsm[];
    const uint32_t smb = smem_u32(dynsm);
    const int tid = threadIdx.x;
    const int l = tid & 31;
    const int wid = tid >> 5;
    const int wm = (wid & 3) * 32;
    const int wn = (wid >> 2) * 64;
    const int bm = blockIdx.y * BM;
    const int bn = blockIdx.x * BN;
    const int z = blockIdx.z;

    const float* A = (z == 0) ? a0 : (z == 1) ? a1 : a2;
    const float* W = (z == 0) ? w0 : (z == 1) ? w1 : w2;
    const float* bias = (z == 0) ? bias0 : (z == 1) ? bias1 : bias2;
    const float osc = (z == 0) ? s0 : (z == 1) ? s1 : s2;
    __nv_bfloat16* Chi = (z == 0) ? C0h : (z == 1) ? C1h : C2h;
    __nv_bfloat16* Clo = (z == 0) ? C0l : (z == 1) ? C1l : C2l;

    float acc[2][8][4];
    #pragma unroll
    for (int mi = 0; mi < 2; mi++)
        #pragma unroll
        for (int nj = 0; nj < 8; nj++)
            #pragma unroll
            for (int q = 0; q < 4; q++) acc[mi][nj][q] = 0.0f;

    auto issue = [&](int c, int buf) {
        const int kk = c * BK;
        const uint32_t base = smb + buf * BUF;
        #pragma unroll
        for (int i = 0; i < 4; i++) {
            int idx = tid + i * 256;          // 0..1023
            int row = idx >> 3, s4 = (idx & 7) * 4;
            uint32_t off = (uint32_t)(row * RS + s4) * 4;
            cp16(base + off,       A + (size_t)(bm + row) * KDIM + kk + s4);
            cp16(base + A_T + off, W + (size_t)(bn + row) * KDIM + kk + s4);
        }
        asm volatile("cp.async.commit_group;" ::: "memory");
    };

    // Quadrant row/col for tf32 fragment via ldmatrix-b16 trick
    const int qrow = (l & 7) + ((l >> 3) & 1) * 8;
    const int qcol = (l >> 4) * 4;

    auto compute = [&](int buf) {
        const uint32_t aB = smb + buf * BUF;
        const uint32_t bB = aB + A_T;
        #pragma unroll
        for (int k8 = 0; k8 < 4; k8++) {
            uint32_t a[2][4];
            #pragma unroll
            for (int mi = 0; mi < 2; mi++) {
                uint32_t addr = aB + (uint32_t)((wm + mi * 16 + qrow) * RS
                                                + k8 * 8 + qcol) * 4;
                ldmx4(a[mi][0], a[mi][1], a[mi][2], a[mi][3], addr);
                #pragma unroll
                for (int j = 0; j < 4; j++) a[mi][j] = tf32u(a[mi][j]);
            }
            uint32_t b[4][4];
            #pragma unroll
            for (int p = 0; p < 4; p++) {
                uint32_t addr = bB + (uint32_t)((wn + p * 16 + qrow) * RS
                                                + k8 * 8 + qcol) * 4;
                ldmx4(b[p][0], b[p][1], b[p][2], b[p][3], addr);
                #pragma unroll
                for (int j = 0; j < 4; j++) b[p][j] = tf32u(b[p][j]);
            }
            #pragma unroll
            for (int p = 0; p < 4; p++) {
                #pragma unroll
                for (int mi = 0; mi < 2; mi++) {
                    mma_tf32(acc[mi][2 * p],     a[mi], b[p][0], b[p][2]);
                    mma_tf32(acc[mi][2 * p + 1], a[mi], b[p][1], b[p][3]);
                }
            }
        }
    };

    issue(0, 0);
    issue(1, 1);
    for (int c = 0; c < CHUNKS; ++c) {
        if (c + 1 < CHUNKS) {
            asm volatile("cp.async.wait_group 1;" ::: "memory");
        } else {
            asm volatile("cp.async.wait_group 0;" ::: "memory");
        }
        __syncthreads();
        compute(c % 3);
        __syncthreads();
        if (c + 2 < CHUNKS) issue(c + 2, (c + 2) % 3);
    }

    #pragma unroll
    for (int mi = 0; mi < 2; mi++) {
        int r0 = bm + wm + mi * 16 + (l >> 2);
        #pragma unroll
        for (int nj = 0; nj < 8; nj++) {
            int col = bn + wn + nj * 8 + (l & 3) * 2;
            float2 bv = *(const float2*)&bias[col];
            float v0 = (acc[mi][nj][0] + bv.x) * osc;
            float v1 = (acc[mi][nj][1] + bv.y) * osc;
            float v2 = (acc[mi][nj][2] + bv.x) * osc;
            float v3 = (acc[mi][nj][3] + bv.y) * osc;
            if (SPLIT) {
                uint32_t ph = cvt2bf(v1, v0);
                uint32_t pl = cvt2bf(v1 - bfhi(ph), v0 - bflo(ph));
                *(uint32_t*)&Chi[(size_t)r0 * D_ + col] = ph;
                *(uint32_t*)&Clo[(size_t)r0 * D_ + col] = pl;
                ph = cvt2bf(v3, v2);
                pl = cvt2bf(v3 - bfhi(ph), v2 - bflo(ph));
                *(uint32_t*)&Chi[(size_t)(r0 + 8) * D_ + col] = ph;
                *(uint32_t*)&Clo[(size_t)(r0 + 8) * D_ + col] = pl;
            } else {
                *(float2*)&Cf[(size_t)r0 * D_ + col] = make_float2(v0, v1);
                *(float2*)&Cf[(size_t)(r0 + 8) * D_ + col] = make_float2(v2, v3);
            }
        }
    }
}

// ===========================================================================
// Tensor-core flash attention (bf16 hi/lo, exp2-domain softmax) — R9/R10 core.
// ===========================================================================
__global__ __launch_bounds__(256, 2) void attn_mma(
    const __nv_bfloat16* __restrict__ qHi, const __nv_bfloat16* __restrict__ qLo,
    const __nv_bfloat16* __restrict__ kHi, const __nv_bfloat16* __restrict__ kLo,
    const __nv_bfloat16* __restrict__ vHi, const __nv_bfloat16* __restrict__ vLo,
    const int* __restrict__ mask,
    float* __restrict__ ctx)
{
    extern __shared__ char dynsm[];
    const uint32_t smb = smem_u32(dynsm);
    const int tid = threadIdx.x;
    const int w = tid >> 5, l = tid & 31;
    const int b = blockIdx.z, h = blockIdx.y;
    const int q0 = blockIdx.x * 128;
    const size_t bS = (size_t)b * S_;
    const int hd = h * DK_;

    // Per-tile all-ones flags
    {
        const int4* mp = (const int4*)(mask + b * S_);
        int4 a = mp[tid * 2];
        int4 c = mp[tid * 2 + 1];
        int allm = a.x & a.y & a.z & a.w & c.x & c.y & c.z & c.w;
        allm &= __shfl_xor_sync(0xffffffffu, allm, 1);
        allm &= __shfl_xor_sync(0xffffffffu, allm, 2);
        allm &= __shfl_xor_sync(0xffffffffu, allm, 4);
        if ((tid & 7) == 0)
            ((int*)(dynsm + FLAG_OFF))[tid >> 3] = allm;
    }

    auto load_q = [&](const __nv_bfloat16* g, uint32_t off) {
        #pragma unroll
        for (int t = 0; t < 4; t++) {
            int idx = tid + t * 256;
            int row = idx >> 3, seg = (idx & 7) * 8;
            cp16(smb + off + (uint32_t)(row * SK + seg) * 2,
                 g + (bS + q0 + row) * D_ + hd + seg);
        }
    };
    auto load_kv_tile = [&](const __nv_bfloat16* g, uint32_t off, int tok0) {
        #pragma unroll
        for (int t = 0; t < 2; t++) {
            int idx = tid + t * 256;
            int row = idx >> 3, seg = (idx & 7) * 8;
            cp16(smb + off + (uint32_t)(row * SK + seg) * 2,
                 g + (bS + tok0 + row) * D_ + hd + seg);
        }
    };
    auto load_kv = [&](int kt, int buf) {
        int tok0 = kt * 64;
        load_kv_tile(kHi, KV_OFF(buf, 0), tok0);
        load_kv_tile(kLo, KV_OFF(buf, 1), tok0);
        load_kv_tile(vHi, KV_OFF(buf, 2), tok0);
        load_kv_tile(vLo, KV_OFF(buf, 3), tok0);
        if (tid < 64) cp4(smb + MS_OFF + (uint32_t)(buf * 64 + tid) * 4,
                          mask + b * S_ + tok0 + tid);
    };

    load_q(qHi, QH_OFF);
    load_q(qLo, QL_OFF);
    load_kv(0, 0);
    asm volatile("cp.async.commit_group;" ::: "memory");

    float Oacc[8][4];
    #pragma unroll
    for (int nf = 0; nf < 8; nf++)
        #pragma unroll
        for (int q = 0; q < 4; q++) Oacc[nf][q] = 0.0f;
    float mrun0 = -1e30f, mrun1 = -1e30f, lrun0 = 0.0f, lrun1 = 0.0f;

    const uint32_t a_off = (uint32_t)((w * 16 + (l & 15)) * SK + ((l >> 4) << 3)) * 2;
    const int bmat = l >> 3, br8 = l & 7;

    for (int kt = 0; kt < 32; kt++) {
        const int buf = kt & 1;
        if (kt < 31) {
            load_kv(kt + 1, buf ^ 1);
            asm volatile("cp.async.commit_group;" ::: "memory");
            asm volatile("cp.async.wait_group 1;" ::: "memory");
        } else {
            asm volatile("cp.async.wait_group 0;" ::: "memory");
        }
        __syncthreads();

        const uint32_t KhB = smb + KV_OFF(buf, 0), KlB = smb + KV_OFF(buf, 1);
        const uint32_t VhB = smb + KV_OFF(buf, 2), VlB = smb + KV_OFF(buf, 3);

        float sacc[8][4];
        #pragma unroll
        for (int f = 0; f < 8; f++)
            #pragma unroll
            for (int q = 0; q < 4; q++) sacc[f][q] = 0.0f;

        #pragma unroll
        for (int kc = 0; kc < 4; kc++) {
            uint32_t aH[4], aL[4];
            ldmx4(aH[0], aH[1], aH[2], aH[3], smb + QH_OFF + a_off + kc * 32);
            ldmx4(aL[0], aL[1], aL[2], aL[3], smb + QL_OFF + a_off + kc * 32);
            #pragma unroll
            for (int np = 0; np < 4; np++) {
                uint32_t badr = (uint32_t)((np * 16 + ((bmat >> 1) << 3) + br8) * SK
                                           + kc * 16 + ((bmat & 1) << 3)) * 2;
                uint32_t bh0, bh1, bh2, bh3, bl0, bl1, bl2, bl3;
                ldmx4(bh0, bh1, bh2, bh3, KhB + badr);
                ldmx4(bl0, bl1, bl2, bl3, KlB + badr);
                mma16816(sacc[2 * np],     aH, bh0, bh1);
                mma16816(sacc[2 * np + 1], aH, bh2, bh3);
                mma16816(sacc[2 * np],     aH, bl0, bl1);
                mma16816(sacc[2 * np + 1], aH, bl2, bl3);
                mma16816(sacc[2 * np],     aL, bh0, bh1);
                mma16816(sacc[2 * np + 1], aL, bh2, bh3);
            }
        }

        const int allm = ((const int*)(dynsm + FLAG_OFF))[kt];
        float mx0 = -1e30f, mx1 = -1e30f;
        if (allm) {
            #pragma unroll
            for (int f = 0; f < 8; f++) {
                mx0 = fmaxf(mx0, fmaxf(sacc[f][0], sacc[f][1]));
                mx1 = fmaxf(mx1, fmaxf(sacc[f][2], sacc[f][3]));
            }
        } else {
            const int* ms = (const int*)(dynsm + MS_OFF + buf * 256);
            #pragma unroll
            for (int f = 0; f < 8; f++) {
                int c0 = f * 8 + (l & 3) * 2;
                int mk0 = ms[c0], mk1 = ms[c0 + 1];
                float t0 = mk0 ? sacc[f][0] : -1e30f;
                float t1 = mk1 ? sacc[f][1] : -1e30f;
                float t2 = mk0 ? sacc[f][2] : -1e30f;
                float t3 = mk1 ? sacc[f][3] : -1e30f;
                sacc[f][0] = t0; sacc[f][1] = t1; sacc[f][2] = t2; sacc[f][3] = t3;
                mx0 = fmaxf(mx0, fmaxf(t0, t1));
                mx1 = fmaxf(mx1, fmaxf(t2, t3));
            }
        }
        mx0 = fmaxf(mx0, __shfl_xor_sync(0xffffffffu, mx0, 1));
        mx0 = fmaxf(mx0, __shfl_xor_sync(0xffffffffu, mx0, 2));
        mx1 = fmaxf(mx1, __shfl_xor_sync(0xffffffffu, mx1, 1));
        mx1 = fmaxf(mx1, __shfl_xor_sync(0xffffffffu, mx1, 2));
        float mn0 = fmaxf(mrun0, mx0), mn1 = fmaxf(mrun1, mx1);
        float cor0 = ex2f(mrun0 - mn0), cor1 = ex2f(mrun1 - mn1);
        mrun0 = mn0; mrun1 = mn1;
        float sum0 = 0.0f, sum1 = 0.0f;
        #pragma unroll
        for (int f = 0; f < 8; f++) {
            float p0 = ex2f(sacc[f][0] - mn0);
            float p1 = ex2f(sacc[f][1] - mn0);
            float p2 = ex2f(sacc[f][2] - mn1);
            float p3 = ex2f(sacc[f][3] - mn1);
            sacc[f][0] = p0; sacc[f][1] = p1; sacc[f][2] = p2; sacc[f][3] = p3;
            sum0 += p0 + p1; sum1 += p2 + p3;
        }
        sum0 += __shfl_xor_sync(0xffffffffu, sum0, 1);
        sum0 += __shfl_xor_sync(0xffffffffu, sum0, 2);
        sum1 += __shfl_xor_sync(0xffffffffu, sum1, 1);
        sum1 += __shfl_xor_sync(0xffffffffu, sum1, 2);
        lrun0 = lrun0 * cor0 + sum0;
        lrun1 = lrun1 * cor1 + sum1;
        #pragma unroll
        for (int nf = 0; nf < 8; nf++) {
            Oacc[nf][0] *= cor0; Oacc[nf][1] *= cor0;
            Oacc[nf][2] *= cor1; Oacc[nf][3] *= cor1;
        }

        #pragma unroll
        for (int kc2 = 0; kc2 < 4; kc2++) {
            const float* f0 = sacc[2 * kc2];
            const float* f1 = sacc[2 * kc2 + 1];
            uint32_t aH2[4], aL2[4];
            aH2[0] = cvt2bf(f0[1], f0[0]);
            aH2[1] = cvt2bf(f0[3], f0[2]);
            aH2[2] = cvt2bf(f1[1], f1[0]);
            aH2[3] = cvt2bf(f1[3], f1[2]);
            aL2[0] = cvt2bf(f0[1] - bfhi(aH2[0]), f0[0] - bflo(aH2[0]));
            aL2[1] = cvt2bf(f0[3] - bfhi(aH2[1]), f0[2] - bflo(aH2[1]));
            aL2[2] = cvt2bf(f1[1] - bfhi(aH2[2]), f1[0] - bflo(aH2[2]));
            aL2[3] = cvt2bf(f1[3] - bfhi(aH2[3]), f1[2] - bflo(aH2[3]));
            #pragma unroll
            for (int nf = 0; nf < 4; nf++) {
                uint32_t vadr = (uint32_t)((kc2 * 16 + (l & 15)) * SK
                                           + nf * 16 + ((l >> 4) << 3)) * 2;
                uint32_t vh0, vh1, vh2, vh3, vl0, vl1, vl2, vl3;
                ldmx4t(vh0, vh1, vh2, vh3, VhB + vadr);
                ldmx4t(vl0, vl1, vl2, vl3, VlB + vadr);
                mma16816(Oacc[2 * nf],     aH2, vh0, vh1);
                mma16816(Oacc[2 * nf + 1], aH2, vh2, vh3);
                mma16816(Oacc[2 * nf],     aH2, vl0, vl1);
                mma16816(Oacc[2 * nf + 1], aH2, vl2, vl3);
                mma16816(Oacc[2 * nf],     aL2, vh0, vh1);
                mma16816(Oacc[2 * nf + 1], aL2, vh2, vh3);
            }
        }
        __syncthreads();
    }

    // Epilogue: normalize, write fp32 ctx (tf32 rounding happens in out-proj)
    const float inv0 = 1.0f / lrun0;
    const float inv1 = 1.0f / lrun1;
    const int r0 = q0 + w * 16 + (l >> 2);
    #pragma unroll
    for (int nf = 0; nf < 8; nf++) {
        int col = hd + nf * 8 + (l & 3) * 2;
        float2 o0, o1;
        o0.x = Oacc[nf][0] * inv0;
        o0.y = Oacc[nf][1] * inv0;
        o1.x = Oacc[nf][2] * inv1;
        o1.y = Oacc[nf][3] * inv1;
        *(float2*)&ctx[(bS + r0) * D_ + col] = o0;
        *(float2*)&ctx[(bS + r0 + 8) * D_ + col] = o1;
    }
}

// ---------------------------------------------------------------------------
extern "C" void kernel_launch(void* const* d_in, const int* in_sizes, int n_in,
                              void* d_out, int out_size)
{
    (void)in_sizes; (void)n_in; (void)out_size;
    const float* query = (const float*)d_in[0];
    const float* key   = (const float*)d_in[1];
    const float* value = (const float*)d_in[2];
    const int*   mask  = (const int*)d_in[3];
    const float* Wq = (const float*)d_in[4];
    const float* bq = (const float*)d_in[5];
    const float* Wk = (const float*)d_in[6];
    const float* bk = (const float*)d_in[7];
    const float* Wv = (const float*)d_in[8];
    const float* bv = (const float*)d_in[9];
    const float* Wo = (const float*)d_in[10];
    const float* bo = (const float*)d_in[11];
    float* out = (float*)d_out;

    __nv_bfloat16 *qh, *ql, *kh, *kl, *vh, *vl;
    float *ctx;
    cudaGetSymbolAddress((void**)&qh, g_qh);   cudaGetSymbolAddress((void**)&ql, g_ql);
    cudaGetSymbolAddress((void**)&kh, g_kh);   cudaGetSymbolAddress((void**)&kl, g_kl);
    cudaGetSymbolAddress((void**)&vh, g_vh);   cudaGetSymbolAddress((void**)&vl, g_vl);
    cudaGetSymbolAddress((void**)&ctx, g_ctx);

    const float SC2 = 0.18033688011112042f;   // 0.125 * log2(e)

    cudaFuncSetAttribute(gemm_tf32<true>, cudaFuncAttributeMaxDynamicSharedMemorySize,
                         GEMM_SMEM);
    cudaFuncSetAttribute(gemm_tf32<false>, cudaFuncAttributeMaxDynamicSharedMemorySize,
                         GEMM_SMEM);
    cudaFuncSetAttribute(attn_mma, cudaFuncAttributeMaxDynamicSharedMemorySize,
                         ATTN_SMEM);

    // Fused Q/K/V projections (tf32 single-pass, in-register rounding);
    // Q pre-scaled into exp2 domain
    dim3 ggrid(D_ / BN, (B_ * S_) / BM, 3);
    gemm_tf32<true><<<ggrid, 256, GEMM_SMEM>>>(
        query, Wq, bq,
        key,   Wk, bk,
        value, Wv, bv,
        SC2, 1.0f, 1.0f,
        nullptr, qh, ql, kh, kl, vh, vl);

    // Attention (bf16 hi/lo) -> fp32 ctx
    dim3 agrid(S_ / 128, H_, B_);
    attn_mma<<<agrid, 256, ATTN_SMEM>>>(qh, ql, kh, kl, vh, vl, mask, ctx);

    // Output projection (tf32 single-pass, fp32 out)
    dim3 ogrid(D_ / BN, (B_ * S_) / BM, 1);
    gemm_tf32<false><<<ogrid, 256, GEMM_SMEM>>>(
        ctx, Wo, bo,
        ctx, Wo, bo,
        ctx, Wo, bo,
        1.0f, 1.0f, 1.0f,
        out, nullptr, nullptr, nullptr, nullptr, nullptr, nullptr);
}

// round 12
// speedup vs baseline: 1.2290x; 1.0471x over previous
#include <cuda_runtime.h>
#include <cuda_bf16.h>
#include <math.h>
#include <stdint.h>

// Problem constants
#define B_  2
#define S_  2048
#define D_  1024
#define H_  16
#define DK_ 64

// GEMM tiling (tf32): 128x128 tile, 256 threads, 3-stage, 2 CTAs/SM
#define BM 128
#define BN 128
#define BK 32
#define KDIM 1024
#define CHUNKS 32
#define RS 36                            // fp32 row stride (bank-conflict-free)
#define A_T (128 * RS * 4)               // 18432 B
#define B_T (128 * RS * 4)
#define BUF (A_T + B_T)                  // 36864
#define GEMM_SMEM (3 * BUF)              // 110592

// Attention smem layout (64-key tiles, 2 CTAs/SM)
#define SK 72
#define QT_B (128 * SK * 2)
#define KT_B (64 * SK * 2)
#define QH_OFF 0
#define QL_OFF QT_B
#define KV_OFF(buf, t) (2 * QT_B + (buf) * 4 * KT_B + (t) * KT_B)
#define MS_OFF (2 * QT_B + 8 * KT_B)
#define FLAG_OFF (MS_OFF + 512)
#define ATTN_SMEM (FLAG_OFF + 128)

// Scratch (device globals)
__device__ __nv_bfloat16 g_qh[B_*S_*D_], g_ql[B_*S_*D_];
__device__ __nv_bfloat16 g_kh[B_*S_*D_], g_kl[B_*S_*D_];
__device__ __nv_bfloat16 g_vh[B_*S_*D_], g_vl[B_*S_*D_];
__device__ float g_ctx[B_*S_*D_];

// ===========================================================================
// Helpers
// ===========================================================================
__device__ __forceinline__ uint32_t smem_u32(const void* p) {
    uint32_t a;
    asm("{ .reg .u64 t; cvta.to.shared.u64 t, %1; cvt.u32.u64 %0, t; }"
        : "=r"(a) : "l"(p));
    return a;
}
__device__ __forceinline__ void cp16(uint32_t dst, const void* src) {
    asm volatile("cp.async.cg.shared.global [%0], [%1], 16;" :: "r"(dst), "l"(src));
}
__device__ __forceinline__ void cp4(uint32_t dst, const void* src) {
    asm volatile("cp.async.ca.shared.global [%0], [%1], 4;" :: "r"(dst), "l"(src));
}
__device__ __forceinline__ void ldmx4(uint32_t& r0, uint32_t& r1,
                                      uint32_t& r2, uint32_t& r3, uint32_t addr) {
    asm volatile("ldmatrix.sync.aligned.m8n8.x4.shared.b16 {%0,%1,%2,%3}, [%4];"
                 : "=r"(r0), "=r"(r1), "=r"(r2), "=r"(r3) : "r"(addr));
}
__device__ __forceinline__ void ldmx4t(uint32_t& r0, uint32_t& r1,
                                       uint32_t& r2, uint32_t& r3, uint32_t addr) {
    asm volatile("ldmatrix.sync.aligned.m8n8.x4.trans.shared.b16 {%0,%1,%2,%3}, [%4];"
                 : "=r"(r0), "=r"(r1), "=r"(r2), "=r"(r3) : "r"(addr));
}
__device__ __forceinline__ void mma16816(float* c, const uint32_t* a,
                                         uint32_t b0, uint32_t b1) {
    asm volatile(
        "mma.sync.aligned.m16n8k16.row.col.f32.bf16.bf16.f32 "
        "{%0,%1,%2,%3}, {%4,%5,%6,%7}, {%8,%9}, {%0,%1,%2,%3};"
        : "+f"(c[0]), "+f"(c[1]), "+f"(c[2]), "+f"(c[3])
        : "r"(a[0]), "r"(a[1]), "r"(a[2]), "r"(a[3]), "r"(b0), "r"(b1));
}
__device__ __forceinline__ void mma_tf32(float* c, const uint32_t* a,
                                         uint32_t b0, uint32_t b1) {
    asm volatile(
        "mma.sync.aligned.m16n8k8.row.col.f32.tf32.tf32.f32 "
        "{%0,%1,%2,%3}, {%4,%5,%6,%7}, {%8,%9}, {%0,%1,%2,%3};"
        : "+f"(c[0]), "+f"(c[1]), "+f"(c[2]), "+f"(c[3])
        : "r"(a[0]), "r"(a[1]), "r"(a[2]), "r"(a[3]), "r"(b0), "r"(b1));
}
__device__ __forceinline__ uint32_t cvt2bf(float hi_elem, float lo_elem) {
    uint32_t r;
    asm("cvt.rn.bf16x2.f32 %0, %1, %2;" : "=r"(r) : "f"(hi_elem), "f"(lo_elem));
    return r;
}
__device__ __forceinline__ float bflo(uint32_t p) { return __uint_as_float(p << 16); }
__device__ __forceinline__ float bfhi(uint32_t p) { return __uint_as_float(p & 0xFFFF0000u); }
__device__ __forceinline__ float ex2f(float x) {
    float y; asm("ex2.approx.f32 %0, %1;" : "=f"(y) : "f"(x)); return y;
}

// ===========================================================================
// TF32 GEMM (NT + bias, optional output scale): 128x128, 256 thr, 2 CTAs/SM.
// Raw fp32 operands fed to tf32 mma (hardware mantissa truncation).
// 3-stage cp.async pipeline, single barrier per chunk.
// SPLIT -> bf16 hi/lo outputs; else fp32.
// ===========================================================================
template<bool SPLIT>
__global__ __launch_bounds__(256, 2) void gemm_tf32(
    const float* __restrict__ a0, const float* __restrict__ w0,
    const float* __restrict__ bias0,
    const float* __restrict__ a1, const float* __restrict__ w1,
    const float* __restrict__ bias1,
    const float* __restrict__ a2, const float* __restrict__ w2,
    const float* __restrict__ bias2,
    float s0, float s1, float s2,
    float* __restrict__ Cf,
    __nv_bfloat16* __restrict__ C0h, __nv_bfloat16* __restrict__ C0l,
    __nv_bfloat16* __restrict__ C1h, __nv_bfloat16* __restrict__ C1l,
    __nv_bfloat16* __restrict__ C2h, __nv_bfloat16* __restrict__ C2l)
{
    extern __shared__ char dynsm[];
    const uint32_t smb = smem_u32(dynsm);
    const int tid = threadIdx.x;
    const int l = tid & 31;
    const int wid = tid >> 5;
    const int wm = (wid & 3) * 32;
    const int wn = (wid >> 2) * 64;
    const int bm = blockIdx.y * BM;
    const int bn = blockIdx.x * BN;
    const int z = blockIdx.z;

    const float* A = (z == 0) ? a0 : (z == 1) ? a1 : a2;
    const float* W = (z == 0) ? w0 : (z == 1) ? w1 : w2;
    const float* bias = (z == 0) ? bias0 : (z == 1) ? bias1 : bias2;
    const float osc = (z == 0) ? s0 : (z == 1) ? s1 : s2;
    __nv_bfloat16* Chi = (z == 0) ? C0h : (z == 1) ? C1h : C2h;
    __nv_bfloat16* Clo = (z == 0) ? C0l : (z == 1) ? C1l : C2l;

    float acc[2][8][4];
    #pragma unroll
    for (int mi = 0; mi < 2; mi++)
        #pragma unroll
        for (int nj = 0; nj < 8; nj++)
            #pragma unroll
            for (int q = 0; q < 4; q++) acc[mi][nj][q] = 0.0f;

    auto issue = [&](int c, int buf) {
        const int kk = c * BK;
        const uint32_t base = smb + buf * BUF;
        #pragma unroll
        for (int i = 0; i < 4; i++) {
            int idx = tid + i * 256;          // 0..1023
            int row = idx >> 3, s4 = (idx & 7) * 4;
            uint32_t off = (uint32_t)(row * RS + s4) * 4;
            cp16(base + off,       A + (size_t)(bm + row) * KDIM + kk + s4);
            cp16(base + A_T + off, W + (size_t)(bn + row) * KDIM + kk + s4);
        }
        asm volatile("cp.async.commit_group;" ::: "memory");
    };

    // Quadrant row/col for tf32 fragment via ldmatrix-b16 trick
    const int qrow = (l & 7) + ((l >> 3) & 1) * 8;
    const int qcol = (l >> 4) * 4;

    auto compute = [&](int buf) {
        const uint32_t aB = smb + buf * BUF;
        const uint32_t bB = aB + A_T;
        #pragma unroll
        for (int k8 = 0; k8 < 4; k8++) {
            uint32_t a[2][4];
            #pragma unroll
            for (int mi = 0; mi < 2; mi++) {
                uint32_t addr = aB + (uint32_t)((wm + mi * 16 + qrow) * RS
                                                + k8 * 8 + qcol) * 4;
                ldmx4(a[mi][0], a[mi][1], a[mi][2], a[mi][3], addr);
            }
            uint32_t b[4][4];
            #pragma unroll
            for (int p = 0; p < 4; p++) {
                uint32_t addr = bB + (uint32_t)((wn + p * 16 + qrow) * RS
                                                + k8 * 8 + qcol) * 4;
                ldmx4(b[p][0], b[p][1], b[p][2], b[p][3], addr);
            }
            #pragma unroll
            for (int p = 0; p < 4; p++) {
                #pragma unroll
                for (int mi = 0; mi < 2; mi++) {
                    mma_tf32(acc[mi][2 * p],     a[mi], b[p][0], b[p][2]);
                    mma_tf32(acc[mi][2 * p + 1], a[mi], b[p][1], b[p][3]);
                }
            }
        }
    };

    issue(0, 0);
    issue(1, 1);
    for (int c = 0; c < CHUNKS; ++c) {
        if (c + 1 < CHUNKS) {
            asm volatile("cp.async.wait_group 1;" ::: "memory");
        } else {
            asm volatile("cp.async.wait_group 0;" ::: "memory");
        }
        __syncthreads();
        // Safe single-barrier 3-stage: issue targets buffer (c+2)%3 == (c-1)%3,
        // whose last readers (compute(c-1)) all passed the barrier above.
        if (c + 2 < CHUNKS) issue(c + 2, (c + 2) % 3);
        compute(c % 3);
    }

    #pragma unroll
    for (int mi = 0; mi < 2; mi++) {
        int r0 = bm + wm + mi * 16 + (l >> 2);
        #pragma unroll
        for (int nj = 0; nj < 8; nj++) {
            int col = bn + wn + nj * 8 + (l & 3) * 2;
            float2 bv = *(const float2*)&bias[col];
            float v0 = (acc[mi][nj][0] + bv.x) * osc;
            float v1 = (acc[mi][nj][1] + bv.y) * osc;
            float v2 = (acc[mi][nj][2] + bv.x) * osc;
            float v3 = (acc[mi][nj][3] + bv.y) * osc;
            if (SPLIT) {
                uint32_t ph = cvt2bf(v1, v0);
                uint32_t pl = cvt2bf(v1 - bfhi(ph), v0 - bflo(ph));
                *(uint32_t*)&Chi[(size_t)r0 * D_ + col] = ph;
                *(uint32_t*)&Clo[(size_t)r0 * D_ + col] = pl;
                ph = cvt2bf(v3, v2);
                pl = cvt2bf(v3 - bfhi(ph), v2 - bflo(ph));
                *(uint32_t*)&Chi[(size_t)(r0 + 8) * D_ + col] = ph;
                *(uint32_t*)&Clo[(size_t)(r0 + 8) * D_ + col] = pl;
            } else {
                *(float2*)&Cf[(size_t)r0 * D_ + col] = make_float2(v0, v1);
                *(float2*)&Cf[(size_t)(r0 + 8) * D_ + col] = make_float2(v2, v3);
            }
        }
    }
}

// ===========================================================================
// Tensor-core flash attention (bf16 hi/lo, exp2-domain softmax) — R9/R10 core.
// ===========================================================================
__global__ __launch_bounds__(256, 2) void attn_mma(
    const __nv_bfloat16* __restrict__ qHi, const __nv_bfloat16* __restrict__ qLo,
    const __nv_bfloat16* __restrict__ kHi, const __nv_bfloat16* __restrict__ kLo,
    const __nv_bfloat16* __restrict__ vHi, const __nv_bfloat16* __restrict__ vLo,
    const int* __restrict__ mask,
    float* __restrict__ ctx)
{
    extern __shared__ char dynsm[];
    const uint32_t smb = smem_u32(dynsm);
    const int tid = threadIdx.x;
    const int w = tid >> 5, l = tid & 31;
    const int b = blockIdx.z, h = blockIdx.y;
    const int q0 = blockIdx.x * 128;
    const size_t bS = (size_t)b * S_;
    const int hd = h * DK_;

    // Per-tile all-ones flags
    {
        const int4* mp = (const int4*)(mask + b * S_);
        int4 a = mp[tid * 2];
        int4 c = mp[tid * 2 + 1];
        int allm = a.x & a.y & a.z & a.w & c.x & c.y & c.z & c.w;
        allm &= __shfl_xor_sync(0xffffffffu, allm, 1);
        allm &= __shfl_xor_sync(0xffffffffu, allm, 2);
        allm &= __shfl_xor_sync(0xffffffffu, allm, 4);
        if ((tid & 7) == 0)
            ((int*)(dynsm + FLAG_OFF))[tid >> 3] = allm;
    }

    auto load_q = [&](const __nv_bfloat16* g, uint32_t off) {
        #pragma unroll
        for (int t = 0; t < 4; t++) {
            int idx = tid + t * 256;
            int row = idx >> 3, seg = (idx & 7) * 8;
            cp16(smb + off + (uint32_t)(row * SK + seg) * 2,
                 g + (bS + q0 + row) * D_ + hd + seg);
        }
    };
    auto load_kv_tile = [&](const __nv_bfloat16* g, uint32_t off, int tok0) {
        #pragma unroll
        for (int t = 0; t < 2; t++) {
            int idx = tid + t * 256;
            int row = idx >> 3, seg = (idx & 7) * 8;
            cp16(smb + off + (uint32_t)(row * SK + seg) * 2,
                 g + (bS + tok0 + row) * D_ + hd + seg);
        }
    };
    auto load_kv = [&](int kt, int buf) {
        int tok0 = kt * 64;
        load_kv_tile(kHi, KV_OFF(buf, 0), tok0);
        load_kv_tile(kLo, KV_OFF(buf, 1), tok0);
        load_kv_tile(vHi, KV_OFF(buf, 2), tok0);
        load_kv_tile(vLo, KV_OFF(buf, 3), tok0);
        if (tid < 64) cp4(smb + MS_OFF + (uint32_t)(buf * 64 + tid) * 4,
                          mask + b * S_ + tok0 + tid);
    };

    load_q(qHi, QH_OFF);
    load_q(qLo, QL_OFF);
    load_kv(0, 0);
    asm volatile("cp.async.commit_group;" ::: "memory");

    float Oacc[8][4];
    #pragma unroll
    for (int nf = 0; nf < 8; nf++)
        #pragma unroll
        for (int q = 0; q < 4; q++) Oacc[nf][q] = 0.0f;
    float mrun0 = -1e30f, mrun1 = -1e30f, lrun0 = 0.0f, lrun1 = 0.0f;

    const uint32_t a_off = (uint32_t)((w * 16 + (l & 15)) * SK + ((l >> 4) << 3)) * 2;
    const int bmat = l >> 3, br8 = l & 7;

    for (int kt = 0; kt < 32; kt++) {
        const int buf = kt & 1;
        if (kt < 31) {
            load_kv(kt + 1, buf ^ 1);
            asm volatile("cp.async.commit_group;" ::: "memory");
            asm volatile("cp.async.wait_group 1;" ::: "memory");
        } else {
            asm volatile("cp.async.wait_group 0;" ::: "memory");
        }
        __syncthreads();

        const uint32_t KhB = smb + KV_OFF(buf, 0), KlB = smb + KV_OFF(buf, 1);
        const uint32_t VhB = smb + KV_OFF(buf, 2), VlB = smb + KV_OFF(buf, 3);

        float sacc[8][4];
        #pragma unroll
        for (int f = 0; f < 8; f++)
            #pragma unroll
            for (int q = 0; q < 4; q++) sacc[f][q] = 0.0f;

        #pragma unroll
        for (int kc = 0; kc < 4; kc++) {
            uint32_t aH[4], aL[4];
            ldmx4(aH[0], aH[1], aH[2], aH[3], smb + QH_OFF + a_off + kc * 32);
            ldmx4(aL[0], aL[1], aL[2], aL[3], smb + QL_OFF + a_off + kc * 32);
            #pragma unroll
            for (int np = 0; np < 4; np++) {
                uint32_t badr = (uint32_t)((np * 16 + ((bmat >> 1) << 3) + br8) * SK
                                           + kc * 16 + ((bmat & 1) << 3)) * 2;
                uint32_t bh0, bh1, bh2, bh3, bl0, bl1, bl2, bl3;
                ldmx4(bh0, bh1, bh2, bh3, KhB + badr);
                ldmx4(bl0, bl1, bl2, bl3, KlB + badr);
                mma16816(sacc[2 * np],     aH, bh0, bh1);
                mma16816(sacc[2 * np + 1], aH, bh2, bh3);
                mma16816(sacc[2 * np],     aH, bl0, bl1);
                mma16816(sacc[2 * np + 1], aH, bl2, bl3);
                mma16816(sacc[2 * np],     aL, bh0, bh1);
                mma16816(sacc[2 * np + 1], aL, bh2, bh3);
            }
        }

        const int allm = ((const int*)(dynsm + FLAG_OFF))[kt];
        float mx0 = -1e30f, mx1 = -1e30f;
        if (allm) {
            #pragma unroll
            for (int f = 0; f < 8; f++) {
                mx0 = fmaxf(mx0, fmaxf(sacc[f][0], sacc[f][1]));
                mx1 = fmaxf(mx1, fmaxf(sacc[f][2], sacc[f][3]));
            }
        } else {
            const int* ms = (const int*)(dynsm + MS_OFF + buf * 256);
            #pragma unroll
            for (int f = 0; f < 8; f++) {
                int c0 = f * 8 + (l & 3) * 2;
                int mk0 = ms[c0], mk1 = ms[c0 + 1];
                float t0 = mk0 ? sacc[f][0] : -1e30f;
                float t1 = mk1 ? sacc[f][1] : -1e30f;
                float t2 = mk0 ? sacc[f][2] : -1e30f;
                float t3 = mk1 ? sacc[f][3] : -1e30f;
                sacc[f][0] = t0; sacc[f][1] = t1; sacc[f][2] = t2; sacc[f][3] = t3;
                mx0 = fmaxf(mx0, fmaxf(t0, t1));
                mx1 = fmaxf(mx1, fmaxf(t2, t3));
            }
        }
        mx0 = fmaxf(mx0, __shfl_xor_sync(0xffffffffu, mx0, 1));
        mx0 = fmaxf(mx0, __shfl_xor_sync(0xffffffffu, mx0, 2));
        mx1 = fmaxf(mx1, __shfl_xor_sync(0xffffffffu, mx1, 1));
        mx1 = fmaxf(mx1, __shfl_xor_sync(0xffffffffu, mx1, 2));
        float mn0 = fmaxf(mrun0, mx0), mn1 = fmaxf(mrun1, mx1);
        float cor0 = ex2f(mrun0 - mn0), cor1 = ex2f(mrun1 - mn1);
        mrun0 = mn0; mrun1 = mn1;
        float sum0 = 0.0f, sum1 = 0.0f;
        #pragma unroll
        for (int f = 0; f < 8; f++) {
            float p0 = ex2f(sacc[f][0] - mn0);
            float p1 = ex2f(sacc[f][1] - mn0);
            float p2 = ex2f(sacc[f][2] - mn1);
            float p3 = ex2f(sacc[f][3] - mn1);
            sacc[f][0] = p0; sacc[f][1] = p1; sacc[f][2] = p2; sacc[f][3] = p3;
            sum0 += p0 + p1; sum1 += p2 + p3;
        }
        sum0 += __shfl_xor_sync(0xffffffffu, sum0, 1);
        sum0 += __shfl_xor_sync(0xffffffffu, sum0, 2);
        sum1 += __shfl_xor_sync(0xffffffffu, sum1, 1);
        sum1 += __shfl_xor_sync(0xffffffffu, sum1, 2);
        lrun0 = lrun0 * cor0 + sum0;
        lrun1 = lrun1 * cor1 + sum1;
        #pragma unroll
        for (int nf = 0; nf < 8; nf++) {
            Oacc[nf][0] *= cor0; Oacc[nf][1] *= cor0;
            Oacc[nf][2] *= cor1; Oacc[nf][3] *= cor1;
        }

        #pragma unroll
        for (int kc2 = 0; kc2 < 4; kc2++) {
            const float* f0 = sacc[2 * kc2];
            const float* f1 = sacc[2 * kc2 + 1];
            uint32_t aH2[4], aL2[4];
            aH2[0] = cvt2bf(f0[1], f0[0]);
            aH2[1] = cvt2bf(f0[3], f0[2]);
            aH2[2] = cvt2bf(f1[1], f1[0]);
            aH2[3] = cvt2bf(f1[3], f1[2]);
            aL2[0] = cvt2bf(f0[1] - bfhi(aH2[0]), f0[0] - bflo(aH2[0]));
            aL2[1] = cvt2bf(f0[3] - bfhi(aH2[1]), f0[2] - bflo(aH2[1]));
            aL2[2] = cvt2bf(f1[1] - bfhi(aH2[2]), f1[0] - bflo(aH2[2]));
            aL2[3] = cvt2bf(f1[3] - bfhi(aH2[3]), f1[2] - bflo(aH2[3]));
            #pragma unroll
            for (int nf = 0; nf < 4; nf++) {
                uint32_t vadr = (uint32_t)((kc2 * 16 + (l & 15)) * SK
                                           + nf * 16 + ((l >> 4) << 3)) * 2;
                uint32_t vh0, vh1, vh2, vh3, vl0, vl1, vl2, vl3;
                ldmx4t(vh0, vh1, vh2, vh3, VhB + vadr);
                ldmx4t(vl0, vl1, vl2, vl3, VlB + vadr);
                mma16816(Oacc[2 * nf],     aH2, vh0, vh1);
                mma16816(Oacc[2 * nf + 1], aH2, vh2, vh3);
                mma16816(Oacc[2 * nf],     aH2, vl0, vl1);
                mma16816(Oacc[2 * nf + 1], aH2, vl2, vl3);
                mma16816(Oacc[2 * nf],     aL2, vh0, vh1);
                mma16816(Oacc[2 * nf + 1], aL2, vh2, vh3);
            }
        }
        __syncthreads();
    }

    // Epilogue: normalize, write fp32 ctx
    const float inv0 = 1.0f / lrun0;
    const float inv1 = 1.0f / lrun1;
    const int r0 = q0 + w * 16 + (l >> 2);
    #pragma unroll
    for (int nf = 0; nf < 8; nf++) {
        int col = hd + nf * 8 + (l & 3) * 2;
        float2 o0, o1;
        o0.x = Oacc[nf][0] * inv0;
        o0.y = Oacc[nf][1] * inv0;
        o1.x = Oacc[nf][2] * inv1;
        o1.y = Oacc[nf][3] * inv1;
        *(float2*)&ctx[(bS + r0) * D_ + col] = o0;
        *(float2*)&ctx[(bS + r0 + 8) * D_ + col] = o1;
    }
}

// ---------------------------------------------------------------------------
extern "C" void kernel_launch(void* const* d_in, const int* in_sizes, int n_in,
                              void* d_out, int out_size)
{
    (void)in_sizes; (void)n_in; (void)out_size;
    const float* query = (const float*)d_in[0];
    const float* key   = (const float*)d_in[1];
    const float* value = (const float*)d_in[2];
    const int*   mask  = (const int*)d_in[3];
    const float* Wq = (const float*)d_in[4];
    const float* bq = (const float*)d_in[5];
    const float* Wk = (const float*)d_in[6];
    const float* bk = (const float*)d_in[7];
    const float* Wv = (const float*)d_in[8];
    const float* bv = (const float*)d_in[9];
    const float* Wo = (const float*)d_in[10];
    const float* bo = (const float*)d_in[11];
    float* out = (float*)d_out;

    __nv_bfloat16 *qh, *ql, *kh, *kl, *vh, *vl;
    float *ctx;
    cudaGetSymbolAddress((void**)&qh, g_qh);   cudaGetSymbolAddress((void**)&ql, g_ql);
    cudaGetSymbolAddress((void**)&kh, g_kh);   cudaGetSymbolAddress((void**)&kl, g_kl);
    cudaGetSymbolAddress((void**)&vh, g_vh);   cudaGetSymbolAddress((void**)&vl, g_vl);
    cudaGetSymbolAddress((void**)&ctx, g_ctx);

    const float SC2 = 0.18033688011112042f;   // 0.125 * log2(e)

    cudaFuncSetAttribute(gemm_tf32<true>, cudaFuncAttributeMaxDynamicSharedMemorySize,
                         GEMM_SMEM);
    cudaFuncSetAttribute(gemm_tf32<false>, cudaFuncAttributeMaxDynamicSharedMemorySize,
                         GEMM_SMEM);
    cudaFuncSetAttribute(attn_mma, cudaFuncAttributeMaxDynamicSharedMemorySize,
                         ATTN_SMEM);

    // Fused Q/K/V projections (tf32 single-pass, raw-bit operands);
    // Q pre-scaled into exp2 domain
    dim3 ggrid(D_ / BN, (B_ * S_) / BM, 3);
    gemm_tf32<true><<<ggrid, 256, GEMM_SMEM>>>(
        query, Wq, bq,
        key,   Wk, bk,
        value, Wv, bv,
        SC2, 1.0f, 1.0f,
        nullptr, qh, ql, kh, kl, vh, vl);

    // Attention (bf16 hi/lo) -> fp32 ctx
    dim3 agrid(S_ / 128, H_, B_);
    attn_mma<<<agrid, 256, ATTN_SMEM>>>(qh, ql, kh, kl, vh, vl, mask, ctx);

    // Output projection (tf32 single-pass, fp32 out)
    dim3 ogrid(D_ / BN, (B_ * S_) / BM, 1);
    gemm_tf32<false><<<ogrid, 256, GEMM_SMEM>>>(
        ctx, Wo, bo,
        ctx, Wo, bo,
        ctx, Wo, bo,
        1.0f, 1.0f, 1.0f,
        out, nullptr, nullptr, nullptr, nullptr, nullptr, nullptr);
}